// round 9
// baseline (speedup 1.0000x reference)
#include <cuda_runtime.h>
#include <cuda_bf16.h>
#include <cstdint>
#include <math.h>

// Problem constants
#define B_  2
#define L_  2048
#define D_  1024
#define H_  16
#define DK_ 64
#define M_  (B_ * L_)   // 4096

// ---------------------------------------------------------------------------
// Scratch (device globals; no allocation allowed)
// ---------------------------------------------------------------------------
__device__ __nv_bfloat16 g_Qh[(size_t)M_ * D_];     // [B,H,L,DK] hi (scaled)
__device__ __nv_bfloat16 g_Ql[(size_t)M_ * D_];     // lo
__device__ __nv_bfloat16 g_KhP[(size_t)M_ * D_];
__device__ __nv_bfloat16 g_KlP[(size_t)M_ * D_];
__device__ __nv_bfloat16 g_VhP[(size_t)M_ * D_];
__device__ __nv_bfloat16 g_VlP[(size_t)M_ * D_];
__device__ __nv_bfloat16 g_Wp[4][2][(size_t)D_ * D_];   // weight hi/lo planes
__device__ __nv_bfloat16 g_Xp[3][2][(size_t)M_ * D_];   // q/k/v input hi/lo planes
__device__ __nv_bfloat16 g_Ap[2][(size_t)M_ * D_];      // attn-out hi/lo planes

// ---------------------------------------------------------------------------
// PTX helpers (base-ISA: ldmatrix / mma.sync / cp.async)
// ---------------------------------------------------------------------------
__device__ __forceinline__ uint32_t smem_u32(const void* p) {
    uint32_t a;
    asm("{ .reg .u64 t; cvta.to.shared.u64 t, %1; cvt.u32.u64 %0, t; }" : "=r"(a) : "l"(p));
    return a;
}

#define CP_ASYNC16(dst, src) \
    asm volatile("cp.async.cg.shared.global [%0], [%1], 16;" :: "r"(dst), "l"(src) : "memory")
#define CP_COMMIT() asm volatile("cp.async.commit_group;" ::: "memory")
#define CP_WAIT2()  asm volatile("cp.async.wait_group 2;" ::: "memory")
#define CP_WAIT1()  asm volatile("cp.async.wait_group 1;" ::: "memory")

__device__ __forceinline__ void ldm_x4(uint32_t* r, uint32_t addr) {
    asm volatile("ldmatrix.sync.aligned.m8n8.x4.shared.b16 {%0,%1,%2,%3}, [%4];"
                 : "=r"(r[0]), "=r"(r[1]), "=r"(r[2]), "=r"(r[3]) : "r"(addr));
}
__device__ __forceinline__ void ldm_x4t(uint32_t* r, uint32_t addr) {
    asm volatile("ldmatrix.sync.aligned.m8n8.x4.trans.shared.b16 {%0,%1,%2,%3}, [%4];"
                 : "=r"(r[0]), "=r"(r[1]), "=r"(r[2]), "=r"(r[3]) : "r"(addr));
}
__device__ __forceinline__ void ldm_x2t(uint32_t* r, uint32_t addr) {
    asm volatile("ldmatrix.sync.aligned.m8n8.x2.trans.shared.b16 {%0,%1}, [%2];"
                 : "=r"(r[0]), "=r"(r[1]) : "r"(addr));
}
__device__ __forceinline__ void mma_bf16(float* d, const uint32_t* a, const uint32_t* b) {
    asm volatile("mma.sync.aligned.m16n8k16.row.col.f32.bf16.bf16.f32 "
                 "{%0,%1,%2,%3}, {%4,%5,%6,%7}, {%8,%9}, {%0,%1,%2,%3};"
                 : "+f"(d[0]), "+f"(d[1]), "+f"(d[2]), "+f"(d[3])
                 : "r"(a[0]), "r"(a[1]), "r"(a[2]), "r"(a[3]), "r"(b[0]), "r"(b[1]));
}

// fast exp2 on FMA pipe: valid for t <= 0, clamps below -120. rel err ~2e-6.
__device__ __forceinline__ float exp2p(float t) {
    t = fmaxf(t, -120.0f);
    float r = t + 12582912.0f;          // 1.5 * 2^23: round-to-int in mantissa
    int sc = __float_as_int(r) << 23;   // integer part -> exponent field
    float f = t - (r - 12582912.0f);    // f in [-0.5, 0.5]
    float p = fmaf(f, 1.3333558146e-3f, 9.6178720244e-3f);
    p = fmaf(f, p, 5.5504108665e-2f);
    p = fmaf(f, p, 2.4022650696e-1f);
    p = fmaf(f, p, 6.9314718056e-1f);
    p = fmaf(f, p, 1.0f);
    return __int_as_float(__float_as_int(p) + sc);
}

// split pair (x0, x1) to bf16x2 hi and lo planes
__device__ __forceinline__ void split_pack(float x0, float x1, uint32_t& hp, uint32_t& lp) {
    asm("cvt.rn.bf16x2.f32 %0, %1, %2;" : "=r"(hp) : "f"(x1), "f"(x0));
    float e0 = x0 - __int_as_float((int)(hp << 16));
    float e1 = x1 - __int_as_float((int)(hp & 0xFFFF0000u));
    asm("cvt.rn.bf16x2.f32 %0, %1, %2;" : "=r"(lp) : "f"(e1), "f"(e0));
}

// ---------------------------------------------------------------------------
// Fused fp32 -> (hi, lo) bf16 split: grid.z selects tensor
// ---------------------------------------------------------------------------
struct SplitArgs {
    const float4* src[4];
    uint32_t* hi[4];
    uint32_t* lo[4];
};

__global__ __launch_bounds__(256) void conv_split_multi(SplitArgs args, int n4)
{
    const int z = blockIdx.z;
    const float4* __restrict__ x = args.src[z];
    uint32_t* __restrict__ hi = args.hi[z];
    uint32_t* __restrict__ lo = args.lo[z];
    int i = blockIdx.x * blockDim.x + threadIdx.x;
    int stride = gridDim.x * blockDim.x;
    for (; i < n4; i += stride) {
        float4 v = x[i];
        uint32_t h0, l0h, h1, l1h;
        split_pack(v.x, v.y, h0, l0h);
        split_pack(v.z, v.w, h1, l1h);
        hi[2 * i] = h0; hi[2 * i + 1] = h1;
        lo[2 * i] = l0h; lo[2 * i + 1] = l1h;
    }
}

// ---------------------------------------------------------------------------
// bf16x3 GEMM tile core: 128(M) x 256(N) block, 8 warps (64x64 warp tiles),
// 3-stage cp.async pipeline. K-chunk 32.  (unchanged from round 8)
// ---------------------------------------------------------------------------
#define NSTG      3
#define STG_BYTES 49152
#define BOFF_B    16384
#define GEMM_SMEM (NSTG * STG_BYTES)   // 147456
#define NKT       (D_ / 32)            // 32

__device__ __forceinline__ void gemm_issue_stage(
    uint32_t sb, const __nv_bfloat16* Ahi, const __nv_bfloat16* Alo,
    const __nv_bfloat16* Whi, const __nv_bfloat16* Wlo,
    int bm, int bn, int k0, int tid)
{
#pragma unroll
    for (int i = 0; i < 4; i++) {
        int id = tid + i * 256;
        int r = id >> 3, c16 = id & 7;
        int plane = c16 >> 2, kc = c16 & 3;
        const __nv_bfloat16* src = (plane ? Alo : Ahi) + (size_t)(bm + r) * D_ + k0 + kc * 8;
        uint32_t dst = sb + (uint32_t)r * 128u + (uint32_t)((c16 ^ (r & 7)) << 4);
        CP_ASYNC16(dst, src);
    }
#pragma unroll
    for (int i = 0; i < 8; i++) {
        int id = tid + i * 256;
        int plane = id >> 10, rem = id & 1023;
        int r = rem >> 5, c16 = rem & 31;
        const __nv_bfloat16* src = (plane ? Wlo : Whi) + (size_t)(k0 + r) * D_ + bn + c16 * 8;
        uint32_t dst = sb + BOFF_B + (uint32_t)plane * 16384u +
                       (uint32_t)r * 512u + (uint32_t)((c16 ^ (r & 7)) << 4);
        CP_ASYNC16(dst, src);
    }
}

__device__ __forceinline__ void gemm_mainloop(
    uint32_t sb0, const __nv_bfloat16* Ahi, const __nv_bfloat16* Alo,
    const __nv_bfloat16* Whi, const __nv_bfloat16* Wlo,
    int bm, int bn, int tid, int wm, int wn, int lid, float acc[4][8][4])
{
#pragma unroll
    for (int s = 0; s < 2; s++) {
        gemm_issue_stage(sb0 + s * STG_BYTES, Ahi, Alo, Whi, Wlo, bm, bn, s * 32, tid);
        CP_COMMIT();
    }

    uint32_t stg = 0;
    for (int kt = 0; kt < NKT; kt++) {
        CP_WAIT1();
        __syncthreads();
        const uint32_t sb = sb0 + stg * STG_BYTES;

#pragma unroll
        for (int ks = 0; ks < 2; ks++) {
            uint32_t af[4][2][4];
#pragma unroll
            for (int mi = 0; mi < 4; mi++)
#pragma unroll
                for (int p = 0; p < 2; p++) {
                    int m = wm + mi * 16 + (lid & 15);
                    int c16 = p * 4 + ks * 2 + (lid >> 4);
                    ldm_x4(af[mi][p], sb + (uint32_t)m * 128u + (uint32_t)((c16 ^ (m & 7)) << 4));
                }
            uint32_t bf[8][2][2];
#pragma unroll
            for (int ni = 0; ni < 8; ni++)
#pragma unroll
                for (int p = 0; p < 2; p++) {
                    int k = ks * 16 + (lid & 15);
                    int c16 = (wn >> 3) + ni;
                    uint32_t base = sb + BOFF_B + (uint32_t)p * 16384u;
                    ldm_x2t(bf[ni][p], base + (uint32_t)k * 512u + (uint32_t)((c16 ^ (k & 7)) << 4));
                }
#pragma unroll
            for (int mi = 0; mi < 4; mi++)
#pragma unroll
                for (int ni = 0; ni < 8; ni++) {
                    mma_bf16(acc[mi][ni], af[mi][0], bf[ni][0]);
                    mma_bf16(acc[mi][ni], af[mi][0], bf[ni][1]);
                    mma_bf16(acc[mi][ni], af[mi][1], bf[ni][0]);
                }
        }

        if (kt + 2 < NKT) {
            uint32_t nstg = stg + 2; if (nstg >= 3) nstg -= 3;
            gemm_issue_stage(sb0 + nstg * STG_BYTES,
                             Ahi, Alo, Whi, Wlo, bm, bn, (kt + 2) * 32, tid);
        }
        CP_COMMIT();
        if (++stg == 3) stg = 0;
    }
}

// ---------------------------------------------------------------------------
// Merged QKV projection GEMM: grid.z in {0:Q, 1:K, 2:V}
// ---------------------------------------------------------------------------
struct QkvArgs {
    const __nv_bfloat16* ah[3];
    const __nv_bfloat16* al[3];
    const __nv_bfloat16* wh[3];
    const __nv_bfloat16* wl[3];
    const float* bias[3];
    __nv_bfloat16* oh[3];
    __nv_bfloat16* ol[3];
    float scale[3];
};

__global__ __launch_bounds__(256, 1) void gemm_qkv(QkvArgs args)
{
    extern __shared__ char smem[];
    const uint32_t sb0 = smem_u32(smem);
    const int z = blockIdx.z;
    const int tid = threadIdx.x;
    const int wid = tid >> 5, lid = tid & 31;
    const int bm = blockIdx.y * 128, bn = blockIdx.x * 256;
    const int wm = (wid >> 2) * 64, wn = (wid & 3) * 64;

    float acc[4][8][4];
#pragma unroll
    for (int i = 0; i < 4; i++)
#pragma unroll
        for (int j = 0; j < 8; j++)
#pragma unroll
            for (int k = 0; k < 4; k++) acc[i][j][k] = 0.0f;

    gemm_mainloop(sb0, args.ah[z], args.al[z], args.wh[z], args.wl[z],
                  bm, bn, tid, wm, wn, lid, acc);

    const float* bias = args.bias[z];
    __nv_bfloat16* Pbh = args.oh[z];
    __nv_bfloat16* Pbl = args.ol[z];
    const float scale = args.scale[z];
#pragma unroll
    for (int mi = 0; mi < 4; mi++) {
#pragma unroll
        for (int ni = 0; ni < 8; ni++) {
            int r0 = bm + wm + mi * 16 + (lid >> 2);
            int c0 = bn + wn + ni * 8 + (lid & 3) * 2;
            float b0 = __ldg(bias + c0), b1 = __ldg(bias + c0 + 1);
            float v0 = (acc[mi][ni][0] + b0) * scale, v1 = (acc[mi][ni][1] + b1) * scale;
            float v2 = (acc[mi][ni][2] + b0) * scale, v3 = (acc[mi][ni][3] + b1) * scale;
            uint32_t hp0, lp0, hp1, lp1;
            split_pack(v0, v1, hp0, lp0);
            split_pack(v2, v3, hp1, lp1);
            int h = c0 >> 6, dk = c0 & 63, bb = r0 >> 11, ll = r0 & (L_ - 1);
            size_t base = ((size_t)(bb * H_ + h) * L_) * DK_ + dk;
            *(uint32_t*)&Pbh[base + (size_t)ll * DK_] = hp0;
            *(uint32_t*)&Pbh[base + (size_t)(ll + 8) * DK_] = hp1;
            *(uint32_t*)&Pbl[base + (size_t)ll * DK_] = lp0;
            *(uint32_t*)&Pbl[base + (size_t)(ll + 8) * DK_] = lp1;
        }
    }
}

// ---------------------------------------------------------------------------
// Final projection GEMM: fp32 out [M,N]
// ---------------------------------------------------------------------------
__global__ __launch_bounds__(256, 1) void gemm_out(
    const __nv_bfloat16* __restrict__ Ahi, const __nv_bfloat16* __restrict__ Alo,
    const __nv_bfloat16* __restrict__ Whi, const __nv_bfloat16* __restrict__ Wlo,
    const float* __restrict__ bias, float* __restrict__ C)
{
    extern __shared__ char smem[];
    const uint32_t sb0 = smem_u32(smem);
    const int tid = threadIdx.x;
    const int wid = tid >> 5, lid = tid & 31;
    const int bm = blockIdx.y * 128, bn = blockIdx.x * 256;
    const int wm = (wid >> 2) * 64, wn = (wid & 3) * 64;

    float acc[4][8][4];
#pragma unroll
    for (int i = 0; i < 4; i++)
#pragma unroll
        for (int j = 0; j < 8; j++)
#pragma unroll
            for (int k = 0; k < 4; k++) acc[i][j][k] = 0.0f;

    gemm_mainloop(sb0, Ahi, Alo, Whi, Wlo, bm, bn, tid, wm, wn, lid, acc);

#pragma unroll
    for (int mi = 0; mi < 4; mi++) {
#pragma unroll
        for (int ni = 0; ni < 8; ni++) {
            int r0 = bm + wm + mi * 16 + (lid >> 2);
            int c0 = bn + wn + ni * 8 + (lid & 3) * 2;
            float b0 = __ldg(bias + c0), b1 = __ldg(bias + c0 + 1);
            *(float2*)(C + (size_t)r0 * D_ + c0) =
                make_float2(acc[mi][ni][0] + b0, acc[mi][ni][1] + b1);
            *(float2*)(C + (size_t)(r0 + 8) * D_ + c0) =
                make_float2(acc[mi][ni][2] + b0, acc[mi][ni][3] + b1);
        }
    }
}

// ---------------------------------------------------------------------------
// Tensorized causal flash attention (bf16x3 QK and PV, FMA-pipe exp2).
//   CTA = 64 query rows, 128 threads (4 warps x 16 rows), KT=32 key tiles,
//   3-stage cp.async, 64KB smem + <=170 regs -> 3 CTAs/SM (12 warps) so the
//   softmax scalar chains hide under other warps' mma streams.
// smem: Q hi/lo 16KB @0; 3 stages x (Kh,Kl,Vh,Vl 4KB each) = 48KB @16KB.
// ---------------------------------------------------------------------------
#define KT 32
#define QROWS 64
#define ASTG_BYTES 16384
#define ATTN_SMEM (16384 + 3 * ASTG_BYTES)   // 65536

__global__ __launch_bounds__(128, 3) void attn_mma(
    const __nv_bfloat16* __restrict__ Qh, const __nv_bfloat16* __restrict__ Ql,
    const __nv_bfloat16* __restrict__ Kh, const __nv_bfloat16* __restrict__ Kl,
    const __nv_bfloat16* __restrict__ Vh, const __nv_bfloat16* __restrict__ Vl,
    __nv_bfloat16* __restrict__ Ah, __nv_bfloat16* __restrict__ Al)
{
    extern __shared__ char smem[];
    const uint32_t sb = smem_u32(smem);
    const int tid = threadIdx.x, wid = tid >> 5, lid = tid & 31;
    const int qt = gridDim.x - 1 - blockIdx.x;   // heavy tiles first
    const int bh = blockIdx.y;
    const int qbase = qt * QROWS;
    const int ntiles = 2 * (qt + 1);             // (qbase+64)/KT
    const size_t hbase = (size_t)bh * L_ * DK_;

    // ---- issue Q (group 0): 2 planes x 64 rows x 8 c16 = 1024 chunks ----
    {
        const __nv_bfloat16* qp[2] = { Qh + hbase + (size_t)qbase * DK_,
                                       Ql + hbase + (size_t)qbase * DK_ };
#pragma unroll
        for (int i = 0; i < 8; i++) {
            int id = tid + i * 128;
            int p = id >> 9, rem = id & 511;
            int r = rem >> 3, c16 = rem & 7;
            const __nv_bfloat16* src = qp[p] + (size_t)r * DK_ + c16 * 8;
            uint32_t dst = sb + (uint32_t)p * 8192u + (uint32_t)r * 128u +
                           (uint32_t)((c16 ^ (r & 7)) << 4);
            CP_ASYNC16(dst, src);
        }
        CP_COMMIT();
    }

    const __nv_bfloat16* kv[4] = { Kh + hbase, Kl + hbase, Vh + hbase, Vl + hbase };
    // stage layout: Kh @0, Kl @4096, Vh @8192, Vl @12288 within 16KB stage
#define ISSUE_STAGE(t, buf) do {                                             \
        int _kb = (t) * KT;                                                  \
        uint32_t _so = sb + 16384u + (uint32_t)(buf) * ASTG_BYTES;           \
        _Pragma("unroll")                                                    \
        for (int _i = 0; _i < 8; _i++) {                                     \
            int _id = tid + _i * 128;                                        \
            int _p = _id >> 8, _rem = _id & 255;                             \
            int _r = _rem >> 3, _c = _rem & 7;                               \
            const __nv_bfloat16* _s = kv[_p] + (size_t)(_kb + _r) * DK_ + _c * 8; \
            uint32_t _d = _so + (uint32_t)_p * 4096u + (uint32_t)_r * 128u + \
                          (uint32_t)((_c ^ (_r & 7)) << 4);                  \
            CP_ASYNC16(_d, _s);                                              \
        }                                                                    \
    } while (0)

    ISSUE_STAGE(0, 0); CP_COMMIT();
    ISSUE_STAGE(1, 1); CP_COMMIT();   // ntiles >= 2 always

    uint32_t qfh[4][4], qfl[4][4];
    float O[8][4];
#pragma unroll
    for (int i = 0; i < 8; i++)
#pragma unroll
        for (int j = 0; j < 4; j++) O[i][j] = 0.0f;
    float m0 = -1e30f, m1 = -1e30f, l0 = 0.0f, l1 = 0.0f;

    const int r0g = qbase + 16 * wid + (lid >> 2);
    const int wrow0 = qbase + 16 * wid;

    int buf = 0;   // t % 3
    for (int t = 0; t < ntiles; t++) {
        CP_WAIT1();               // K/V stage t resident (Q done for t=0)
        __syncthreads();

        // prefetch stage t+2 into buffer (t+2)%3 (retired after tile t-1)
        {
            int pbuf = buf + 2; if (pbuf >= 3) pbuf -= 3;
            if (t + 2 < ntiles) ISSUE_STAGE(t + 2, pbuf);
            CP_COMMIT();          // unconditional: keeps group accounting exact
        }

        const uint32_t so = sb + 16384u + (uint32_t)buf * ASTG_BYTES;
        const int kb = t * KT;

        if (t == 0) {
#pragma unroll
            for (int kd = 0; kd < 4; kd++) {
                int row = 16 * wid + (lid & 15);
                int c16 = 2 * kd + (lid >> 4);
                uint32_t a = sb + (uint32_t)row * 128u + (uint32_t)((c16 ^ (row & 7)) << 4);
                ldm_x4(qfh[kd], a);
                ldm_x4(qfl[kd], a + 8192u);
            }
        }

        // ---- S = Q K^T (x3): 16 rows x 32 keys ----
        float S[4][4];
#pragma unroll
        for (int i = 0; i < 4; i++)
#pragma unroll
            for (int j = 0; j < 4; j++) S[i][j] = 0.0f;

#pragma unroll
        for (int kd = 0; kd < 4; kd++) {
#pragma unroll
            for (int p4 = 0; p4 < 2; p4++) {
                int row = p4 * 16 + (lid & 15);
                int c16 = 2 * kd + (lid >> 4);
                uint32_t a = so + (uint32_t)row * 128u + (uint32_t)((c16 ^ (row & 7)) << 4);
                uint32_t kh4[4], kl4[4];
                ldm_x4(kh4, a);             // Kh @0
                ldm_x4(kl4, a + 4096u);     // Kl @4KB
                uint32_t bh0[2] = { kh4[0], kh4[2] }, bh1[2] = { kh4[1], kh4[3] };
                uint32_t bl0[2] = { kl4[0], kl4[2] }, bl1[2] = { kl4[1], kl4[3] };
                mma_bf16(S[2 * p4], qfh[kd], bh0);
                mma_bf16(S[2 * p4], qfh[kd], bl0);
                mma_bf16(S[2 * p4], qfl[kd], bh0);
                mma_bf16(S[2 * p4 + 1], qfh[kd], bh1);
                mma_bf16(S[2 * p4 + 1], qfh[kd], bl1);
                mma_bf16(S[2 * p4 + 1], qfl[kd], bh1);
            }
        }

        // ---- causal mask (diag tiles only) ----
        if (kb + KT > wrow0) {
            int colb = kb + 2 * (lid & 3);
            int r1g = r0g + 8;
#pragma unroll
            for (int ni = 0; ni < 4; ni++) {
                int c = colb + 8 * ni;
                if (c > r0g)     S[ni][0] = -1e30f;
                if (c + 1 > r0g) S[ni][1] = -1e30f;
                if (c > r1g)     S[ni][2] = -1e30f;
                if (c + 1 > r1g) S[ni][3] = -1e30f;
            }
        }

        // ---- online softmax (base-2, FMA-pipe exp) ----
        float t0 = -1e30f, t1 = -1e30f;
#pragma unroll
        for (int ni = 0; ni < 4; ni++) {
            t0 = fmaxf(t0, fmaxf(S[ni][0], S[ni][1]));
            t1 = fmaxf(t1, fmaxf(S[ni][2], S[ni][3]));
        }
        t0 = fmaxf(t0, __shfl_xor_sync(0xFFFFFFFFu, t0, 1));
        t0 = fmaxf(t0, __shfl_xor_sync(0xFFFFFFFFu, t0, 2));
        t1 = fmaxf(t1, __shfl_xor_sync(0xFFFFFFFFu, t1, 1));
        t1 = fmaxf(t1, __shfl_xor_sync(0xFFFFFFFFu, t1, 2));
        float n0 = fmaxf(m0, t0), n1 = fmaxf(m1, t1);
        float c0 = exp2p(m0 - n0), c1 = exp2p(m1 - n1);
        m0 = n0; m1 = n1;
        float s0 = 0.0f, s1 = 0.0f;
#pragma unroll
        for (int ni = 0; ni < 4; ni++) {
            S[ni][0] = exp2p(S[ni][0] - n0); s0 += S[ni][0];
            S[ni][1] = exp2p(S[ni][1] - n0); s0 += S[ni][1];
            S[ni][2] = exp2p(S[ni][2] - n1); s1 += S[ni][2];
            S[ni][3] = exp2p(S[ni][3] - n1); s1 += S[ni][3];
        }
#pragma unroll
        for (int ni = 0; ni < 8; ni++) {
            O[ni][0] *= c0; O[ni][1] *= c0; O[ni][2] *= c1; O[ni][3] *= c1;
        }
        s0 += __shfl_xor_sync(0xFFFFFFFFu, s0, 1);
        s0 += __shfl_xor_sync(0xFFFFFFFFu, s0, 2);
        s1 += __shfl_xor_sync(0xFFFFFFFFu, s1, 1);
        s1 += __shfl_xor_sync(0xFFFFFFFFu, s1, 2);
        l0 = l0 * c0 + s0;
        l1 = l1 * c1 + s1;

        // ---- O += P V (x3), P packed per-ks just-in-time ----
#pragma unroll
        for (int ks = 0; ks < 2; ks++) {
            uint32_t ph[4], pl[4];
            split_pack(S[2 * ks][0], S[2 * ks][1], ph[0], pl[0]);
            split_pack(S[2 * ks][2], S[2 * ks][3], ph[1], pl[1]);
            split_pack(S[2 * ks + 1][0], S[2 * ks + 1][1], ph[2], pl[2]);
            split_pack(S[2 * ks + 1][2], S[2 * ks + 1][3], ph[3], pl[3]);
#pragma unroll
            for (int jp = 0; jp < 4; jp++) {
                int row = ks * 16 + (lid & 15);
                int c16 = 2 * jp + (lid >> 4);
                uint32_t a = so + 8192u + (uint32_t)row * 128u +
                             (uint32_t)((c16 ^ (row & 7)) << 4);
                uint32_t vh4[4], vl4[4];
                ldm_x4t(vh4, a);            // Vh @8KB
                ldm_x4t(vl4, a + 4096u);    // Vl @12KB
                uint32_t bhe[2] = { vh4[0], vh4[1] }, bho[2] = { vh4[2], vh4[3] };
                uint32_t ble[2] = { vl4[0], vl4[1] }, blo[2] = { vl4[2], vl4[3] };
                mma_bf16(O[2 * jp], ph, bhe);
                mma_bf16(O[2 * jp], ph, ble);
                mma_bf16(O[2 * jp], pl, bhe);
                mma_bf16(O[2 * jp + 1], ph, bho);
                mma_bf16(O[2 * jp + 1], ph, blo);
                mma_bf16(O[2 * jp + 1], pl, bho);
            }
        }

        if (++buf == 3) buf = 0;
    }

    // ---- epilogue: normalize, split to bf16 hi/lo, write [B,L,D] ----
    float inv0 = 1.0f / l0, inv1 = 1.0f / l1;
    int b = bh >> 4, h = bh & (H_ - 1);
    size_t base0 = ((size_t)b * L_ + r0g) * D_ + h * DK_ + 2 * (lid & 3);
    size_t base1 = base0 + (size_t)8 * D_;
#pragma unroll
    for (int ni = 0; ni < 8; ni++) {
        uint32_t hp, lp;
        split_pack(O[ni][0] * inv0, O[ni][1] * inv0, hp, lp);
        *(uint32_t*)&Ah[base0 + 8 * ni] = hp;
        *(uint32_t*)&Al[base0 + 8 * ni] = lp;
        split_pack(O[ni][2] * inv1, O[ni][3] * inv1, hp, lp);
        *(uint32_t*)&Ah[base1 + 8 * ni] = hp;
        *(uint32_t*)&Al[base1 + 8 * ni] = lp;
    }
#undef ISSUE_STAGE
}

// ---------------------------------------------------------------------------
// Launch.  Inputs: query, key, value, mask, wq, bq, wk, bk, wv, bv, wo, bo
// ---------------------------------------------------------------------------
extern "C" void kernel_launch(void* const* d_in, const int* in_sizes, int n_in,
                              void* d_out, int out_size)
{
    (void)in_sizes; (void)n_in; (void)out_size;
    const float* query = (const float*)d_in[0];
    const float* key   = (const float*)d_in[1];
    const float* value = (const float*)d_in[2];
    const float* wq = (const float*)d_in[4];
    const float* bq = (const float*)d_in[5];
    const float* wk = (const float*)d_in[6];
    const float* bk = (const float*)d_in[7];
    const float* wv = (const float*)d_in[8];
    const float* bv = (const float*)d_in[9];
    const float* wo = (const float*)d_in[10];
    const float* bo = (const float*)d_in[11];

    __nv_bfloat16 *pQh, *pQl, *pKh, *pKl, *pVh, *pVl, *pWp, *pXp, *pAp;
    cudaGetSymbolAddress((void**)&pQh, g_Qh);
    cudaGetSymbolAddress((void**)&pQl, g_Ql);
    cudaGetSymbolAddress((void**)&pKh, g_KhP);
    cudaGetSymbolAddress((void**)&pKl, g_KlP);
    cudaGetSymbolAddress((void**)&pVh, g_VhP);
    cudaGetSymbolAddress((void**)&pVl, g_VlP);
    cudaGetSymbolAddress((void**)&pWp, g_Wp);
    cudaGetSymbolAddress((void**)&pXp, g_Xp);
    cudaGetSymbolAddress((void**)&pAp, g_Ap);

    cudaFuncSetAttribute(gemm_qkv, cudaFuncAttributeMaxDynamicSharedMemorySize, GEMM_SMEM);
    cudaFuncSetAttribute(gemm_out, cudaFuncAttributeMaxDynamicSharedMemorySize, GEMM_SMEM);
    cudaFuncSetAttribute(attn_mma, cudaFuncAttributeMaxDynamicSharedMemorySize, ATTN_SMEM);

    const size_t WSZ = (size_t)D_ * D_;
    const size_t XSZ = (size_t)M_ * D_;
    __nv_bfloat16 *w_hi[4], *w_lo[4], *x_hi[3], *x_lo[3];
    for (int i = 0; i < 4; i++) {
        w_hi[i] = pWp + (size_t)(2 * i) * WSZ;
        w_lo[i] = pWp + (size_t)(2 * i + 1) * WSZ;
    }
    for (int i = 0; i < 3; i++) {
        x_hi[i] = pXp + (size_t)(2 * i) * XSZ;
        x_lo[i] = pXp + (size_t)(2 * i + 1) * XSZ;
    }
    __nv_bfloat16* a_hi = pAp;
    __nv_bfloat16* a_lo = pAp + XSZ;

    // Fused splits: weights (z=4), inputs (z=3)
    {
        SplitArgs wa = {};
        const float* wsrc[4] = { wq, wk, wv, wo };
        for (int i = 0; i < 4; i++) {
            wa.src[i] = (const float4*)wsrc[i];
            wa.hi[i] = (uint32_t*)w_hi[i];
            wa.lo[i] = (uint32_t*)w_lo[i];
        }
        conv_split_multi<<<dim3(296, 1, 4), 256>>>(wa, (int)(WSZ / 4));

        SplitArgs xa = {};
        const float* xsrc[3] = { query, key, value };
        for (int i = 0; i < 3; i++) {
            xa.src[i] = (const float4*)xsrc[i];
            xa.hi[i] = (uint32_t*)x_hi[i];
            xa.lo[i] = (uint32_t*)x_lo[i];
        }
        conv_split_multi<<<dim3(394, 1, 3), 256>>>(xa, (int)(XSZ / 4));
    }

    // Merged QKV projection (grid.z = 3), 128x256 tiles
    {
        const float QSCALE = 0.18033688011112042f;   // log2(e) / sqrt(DK)
        QkvArgs qa = {};
        const float* biases[3] = { bq, bk, bv };
        __nv_bfloat16* ohs[3] = { pQh, pKh, pVh };
        __nv_bfloat16* ols[3] = { pQl, pKl, pVl };
        for (int i = 0; i < 3; i++) {
            qa.ah[i] = x_hi[i]; qa.al[i] = x_lo[i];
            qa.wh[i] = w_hi[i]; qa.wl[i] = w_lo[i];
            qa.bias[i] = biases[i];
            qa.oh[i] = ohs[i]; qa.ol[i] = ols[i];
            qa.scale[i] = (i == 0) ? QSCALE : 1.0f;
        }
        gemm_qkv<<<dim3(D_ / 256, M_ / 128, 3), 256, GEMM_SMEM>>>(qa);
    }

    dim3 agrid(L_ / QROWS, B_ * H_);   // (32, 32)
    attn_mma<<<agrid, 128, ATTN_SMEM>>>(pQh, pQl, pKh, pKl, pVh, pVl, a_hi, a_lo);

    gemm_out<<<dim3(D_ / 256, M_ / 128), 256, GEMM_SMEM>>>(
        a_hi, a_lo, w_hi[3], w_lo[3], bo, (float*)d_out);
}

// round 10
// speedup vs baseline: 1.0685x; 1.0685x over previous
#include <cuda_runtime.h>
#include <cuda_bf16.h>
#include <cstdint>
#include <math.h>

// Problem constants
#define B_  2
#define L_  2048
#define D_  1024
#define H_  16
#define DK_ 64
#define M_  (B_ * L_)   // 4096

// ---------------------------------------------------------------------------
// Scratch (device globals; no allocation allowed)
// ---------------------------------------------------------------------------
__device__ __nv_bfloat16 g_Qh[(size_t)M_ * D_];     // [B,H,L,DK] hi (scaled)
__device__ __nv_bfloat16 g_Ql[(size_t)M_ * D_];     // lo
__device__ __nv_bfloat16 g_KhP[(size_t)M_ * D_];
__device__ __nv_bfloat16 g_KlP[(size_t)M_ * D_];
__device__ __nv_bfloat16 g_VhP[(size_t)M_ * D_];
__device__ __nv_bfloat16 g_VlP[(size_t)M_ * D_];
__device__ __nv_bfloat16 g_Wp[4][2][(size_t)D_ * D_];   // weight hi/lo planes
__device__ __nv_bfloat16 g_Xp[3][2][(size_t)M_ * D_];   // q/k/v input hi/lo planes
__device__ __nv_bfloat16 g_Ap[2][(size_t)M_ * D_];      // attn-out hi/lo planes

// ---------------------------------------------------------------------------
// PTX helpers (base-ISA: ldmatrix / mma.sync / cp.async)
// ---------------------------------------------------------------------------
__device__ __forceinline__ uint32_t smem_u32(const void* p) {
    uint32_t a;
    asm("{ .reg .u64 t; cvta.to.shared.u64 t, %1; cvt.u32.u64 %0, t; }" : "=r"(a) : "l"(p));
    return a;
}

#define CP_ASYNC16(dst, src) \
    asm volatile("cp.async.cg.shared.global [%0], [%1], 16;" :: "r"(dst), "l"(src) : "memory")
#define CP_COMMIT() asm volatile("cp.async.commit_group;" ::: "memory")
#define CP_WAIT2()  asm volatile("cp.async.wait_group 2;" ::: "memory")
#define CP_WAIT1()  asm volatile("cp.async.wait_group 1;" ::: "memory")

__device__ __forceinline__ void ldm_x4(uint32_t* r, uint32_t addr) {
    asm volatile("ldmatrix.sync.aligned.m8n8.x4.shared.b16 {%0,%1,%2,%3}, [%4];"
                 : "=r"(r[0]), "=r"(r[1]), "=r"(r[2]), "=r"(r[3]) : "r"(addr));
}
__device__ __forceinline__ void ldm_x4t(uint32_t* r, uint32_t addr) {
    asm volatile("ldmatrix.sync.aligned.m8n8.x4.trans.shared.b16 {%0,%1,%2,%3}, [%4];"
                 : "=r"(r[0]), "=r"(r[1]), "=r"(r[2]), "=r"(r[3]) : "r"(addr));
}
__device__ __forceinline__ void mma_bf16(float* d, const uint32_t* a, const uint32_t* b) {
    asm volatile("mma.sync.aligned.m16n8k16.row.col.f32.bf16.bf16.f32 "
                 "{%0,%1,%2,%3}, {%4,%5,%6,%7}, {%8,%9}, {%0,%1,%2,%3};"
                 : "+f"(d[0]), "+f"(d[1]), "+f"(d[2]), "+f"(d[3])
                 : "r"(a[0]), "r"(a[1]), "r"(a[2]), "r"(a[3]), "r"(b[0]), "r"(b[1]));
}

// fast exp2 on FMA pipe, degree-3 poly: valid for t <= 0, clamps below -120.
// Max rel err ~4.6e-4, but common-mode across a softmax row (numerator and
// denominator share it), so the residual on probabilities is ~3e-4.
__device__ __forceinline__ float exp2p(float t) {
    t = fmaxf(t, -120.0f);
    float r = t + 12582912.0f;          // 1.5 * 2^23: round-to-int in mantissa
    int sc = __float_as_int(r) << 23;   // integer part -> exponent field
    float f = t - (r - 12582912.0f);    // f in [-0.5, 0.5]
    float p = fmaf(f, 5.5504108665e-2f, 2.4022650696e-1f);
    p = fmaf(f, p, 6.9314718056e-1f);
    p = fmaf(f, p, 1.0f);
    return __int_as_float(__float_as_int(p) + sc);
}

// split pair (x0, x1) to bf16x2 hi and lo planes
__device__ __forceinline__ void split_pack(float x0, float x1, uint32_t& hp, uint32_t& lp) {
    asm("cvt.rn.bf16x2.f32 %0, %1, %2;" : "=r"(hp) : "f"(x1), "f"(x0));
    float e0 = x0 - __int_as_float((int)(hp << 16));
    float e1 = x1 - __int_as_float((int)(hp & 0xFFFF0000u));
    asm("cvt.rn.bf16x2.f32 %0, %1, %2;" : "=r"(lp) : "f"(e1), "f"(e0));
}

// ---------------------------------------------------------------------------
// Fused fp32 -> (hi, lo) bf16 split: grid.z selects tensor
// ---------------------------------------------------------------------------
struct SplitArgs {
    const float4* src[4];
    uint32_t* hi[4];
    uint32_t* lo[4];
};

__global__ __launch_bounds__(256) void conv_split_multi(SplitArgs args, int n4)
{
    const int z = blockIdx.z;
    const float4* __restrict__ x = args.src[z];
    uint32_t* __restrict__ hi = args.hi[z];
    uint32_t* __restrict__ lo = args.lo[z];
    int i = blockIdx.x * blockDim.x + threadIdx.x;
    int stride = gridDim.x * blockDim.x;
    for (; i < n4; i += stride) {
        float4 v = x[i];
        uint32_t h0, l0h, h1, l1h;
        split_pack(v.x, v.y, h0, l0h);
        split_pack(v.z, v.w, h1, l1h);
        hi[2 * i] = h0; hi[2 * i + 1] = h1;
        lo[2 * i] = l0h; lo[2 * i + 1] = l1h;
    }
}

// ---------------------------------------------------------------------------
// bf16x3 GEMM tile core: 128(M) x 256(N) block, 8 warps (64x64 warp tiles),
// 3-stage cp.async pipeline. K-chunk 32. B fragments via ldm_x4t (4 regs/instr).
// ---------------------------------------------------------------------------
#define NSTG      3
#define STG_BYTES 49152
#define BOFF_B    16384
#define GEMM_SMEM (NSTG * STG_BYTES)   // 147456
#define NKT       (D_ / 32)            // 32

__device__ __forceinline__ void gemm_issue_stage(
    uint32_t sb, const __nv_bfloat16* Ahi, const __nv_bfloat16* Alo,
    const __nv_bfloat16* Whi, const __nv_bfloat16* Wlo,
    int bm, int bn, int k0, int tid)
{
#pragma unroll
    for (int i = 0; i < 4; i++) {
        int id = tid + i * 256;
        int r = id >> 3, c16 = id & 7;
        int plane = c16 >> 2, kc = c16 & 3;
        const __nv_bfloat16* src = (plane ? Alo : Ahi) + (size_t)(bm + r) * D_ + k0 + kc * 8;
        uint32_t dst = sb + (uint32_t)r * 128u + (uint32_t)((c16 ^ (r & 7)) << 4);
        CP_ASYNC16(dst, src);
    }
#pragma unroll
    for (int i = 0; i < 8; i++) {
        int id = tid + i * 256;
        int plane = id >> 10, rem = id & 1023;
        int r = rem >> 5, c16 = rem & 31;
        const __nv_bfloat16* src = (plane ? Wlo : Whi) + (size_t)(k0 + r) * D_ + bn + c16 * 8;
        uint32_t dst = sb + BOFF_B + (uint32_t)plane * 16384u +
                       (uint32_t)r * 512u + (uint32_t)((c16 ^ (r & 7)) << 4);
        CP_ASYNC16(dst, src);
    }
}

__device__ __forceinline__ void gemm_mainloop(
    uint32_t sb0, const __nv_bfloat16* Ahi, const __nv_bfloat16* Alo,
    const __nv_bfloat16* Whi, const __nv_bfloat16* Wlo,
    int bm, int bn, int tid, int wm, int wn, int lid, float acc[4][8][4])
{
#pragma unroll
    for (int s = 0; s < 2; s++) {
        gemm_issue_stage(sb0 + s * STG_BYTES, Ahi, Alo, Whi, Wlo, bm, bn, s * 32, tid);
        CP_COMMIT();
    }

    uint32_t stg = 0;
    for (int kt = 0; kt < NKT; kt++) {
        CP_WAIT1();
        __syncthreads();
        const uint32_t sb = sb0 + stg * STG_BYTES;

#pragma unroll
        for (int ks = 0; ks < 2; ks++) {
            uint32_t af[4][2][4];
#pragma unroll
            for (int mi = 0; mi < 4; mi++)
#pragma unroll
                for (int p = 0; p < 2; p++) {
                    int m = wm + mi * 16 + (lid & 15);
                    int c16 = p * 4 + ks * 2 + (lid >> 4);
                    ldm_x4(af[mi][p], sb + (uint32_t)m * 128u + (uint32_t)((c16 ^ (m & 7)) << 4));
                }
            // B frags via trans x4: one instr covers two adjacent n8 groups.
            uint32_t bf[8][2][2];
#pragma unroll
            for (int nj = 0; nj < 4; nj++)
#pragma unroll
                for (int p = 0; p < 2; p++) {
                    int k = ks * 16 + (lid & 15);
                    int c16 = (wn >> 3) + 2 * nj + (lid >> 4);
                    uint32_t base = sb + BOFF_B + (uint32_t)p * 16384u;
                    uint32_t v4[4];
                    ldm_x4t(v4, base + (uint32_t)k * 512u + (uint32_t)((c16 ^ (k & 7)) << 4));
                    bf[2 * nj][p][0] = v4[0]; bf[2 * nj][p][1] = v4[1];
                    bf[2 * nj + 1][p][0] = v4[2]; bf[2 * nj + 1][p][1] = v4[3];
                }
#pragma unroll
            for (int mi = 0; mi < 4; mi++)
#pragma unroll
                for (int ni = 0; ni < 8; ni++) {
                    mma_bf16(acc[mi][ni], af[mi][0], bf[ni][0]);
                    mma_bf16(acc[mi][ni], af[mi][0], bf[ni][1]);
                    mma_bf16(acc[mi][ni], af[mi][1], bf[ni][0]);
                }
        }

        if (kt + 2 < NKT) {
            uint32_t nstg = stg + 2; if (nstg >= 3) nstg -= 3;
            gemm_issue_stage(sb0 + nstg * STG_BYTES,
                             Ahi, Alo, Whi, Wlo, bm, bn, (kt + 2) * 32, tid);
        }
        CP_COMMIT();
        if (++stg == 3) stg = 0;
    }
}

// ---------------------------------------------------------------------------
// Merged QKV projection GEMM: grid.z in {0:Q, 1:K, 2:V}
// ---------------------------------------------------------------------------
struct QkvArgs {
    const __nv_bfloat16* ah[3];
    const __nv_bfloat16* al[3];
    const __nv_bfloat16* wh[3];
    const __nv_bfloat16* wl[3];
    const float* bias[3];
    __nv_bfloat16* oh[3];
    __nv_bfloat16* ol[3];
    float scale[3];
};

__global__ __launch_bounds__(256, 1) void gemm_qkv(QkvArgs args)
{
    extern __shared__ char smem[];
    const uint32_t sb0 = smem_u32(smem);
    const int z = blockIdx.z;
    const int tid = threadIdx.x;
    const int wid = tid >> 5, lid = tid & 31;
    const int bm = blockIdx.y * 128, bn = blockIdx.x * 256;
    const int wm = (wid >> 2) * 64, wn = (wid & 3) * 64;

    float acc[4][8][4];
#pragma unroll
    for (int i = 0; i < 4; i++)
#pragma unroll
        for (int j = 0; j < 8; j++)
#pragma unroll
            for (int k = 0; k < 4; k++) acc[i][j][k] = 0.0f;

    gemm_mainloop(sb0, args.ah[z], args.al[z], args.wh[z], args.wl[z],
                  bm, bn, tid, wm, wn, lid, acc);

    const float* bias = args.bias[z];
    __nv_bfloat16* Pbh = args.oh[z];
    __nv_bfloat16* Pbl = args.ol[z];
    const float scale = args.scale[z];
#pragma unroll
    for (int mi = 0; mi < 4; mi++) {
#pragma unroll
        for (int ni = 0; ni < 8; ni++) {
            int r0 = bm + wm + mi * 16 + (lid >> 2);
            int c0 = bn + wn + ni * 8 + (lid & 3) * 2;
            float b0 = __ldg(bias + c0), b1 = __ldg(bias + c0 + 1);
            float v0 = (acc[mi][ni][0] + b0) * scale, v1 = (acc[mi][ni][1] + b1) * scale;
            float v2 = (acc[mi][ni][2] + b0) * scale, v3 = (acc[mi][ni][3] + b1) * scale;
            uint32_t hp0, lp0, hp1, lp1;
            split_pack(v0, v1, hp0, lp0);
            split_pack(v2, v3, hp1, lp1);
            int h = c0 >> 6, dk = c0 & 63, bb = r0 >> 11, ll = r0 & (L_ - 1);
            size_t base = ((size_t)(bb * H_ + h) * L_) * DK_ + dk;
            *(uint32_t*)&Pbh[base + (size_t)ll * DK_] = hp0;
            *(uint32_t*)&Pbh[base + (size_t)(ll + 8) * DK_] = hp1;
            *(uint32_t*)&Pbl[base + (size_t)ll * DK_] = lp0;
            *(uint32_t*)&Pbl[base + (size_t)(ll + 8) * DK_] = lp1;
        }
    }
}

// ---------------------------------------------------------------------------
// Final projection GEMM: fp32 out [M,N]
// ---------------------------------------------------------------------------
__global__ __launch_bounds__(256, 1) void gemm_out(
    const __nv_bfloat16* __restrict__ Ahi, const __nv_bfloat16* __restrict__ Alo,
    const __nv_bfloat16* __restrict__ Whi, const __nv_bfloat16* __restrict__ Wlo,
    const float* __restrict__ bias, float* __restrict__ C)
{
    extern __shared__ char smem[];
    const uint32_t sb0 = smem_u32(smem);
    const int tid = threadIdx.x;
    const int wid = tid >> 5, lid = tid & 31;
    const int bm = blockIdx.y * 128, bn = blockIdx.x * 256;
    const int wm = (wid >> 2) * 64, wn = (wid & 3) * 64;

    float acc[4][8][4];
#pragma unroll
    for (int i = 0; i < 4; i++)
#pragma unroll
        for (int j = 0; j < 8; j++)
#pragma unroll
            for (int k = 0; k < 4; k++) acc[i][j][k] = 0.0f;

    gemm_mainloop(sb0, Ahi, Alo, Whi, Wlo, bm, bn, tid, wm, wn, lid, acc);

#pragma unroll
    for (int mi = 0; mi < 4; mi++) {
#pragma unroll
        for (int ni = 0; ni < 8; ni++) {
            int r0 = bm + wm + mi * 16 + (lid >> 2);
            int c0 = bn + wn + ni * 8 + (lid & 3) * 2;
            float b0 = __ldg(bias + c0), b1 = __ldg(bias + c0 + 1);
            *(float2*)(C + (size_t)r0 * D_ + c0) =
                make_float2(acc[mi][ni][0] + b0, acc[mi][ni][1] + b1);
            *(float2*)(C + (size_t)(r0 + 8) * D_ + c0) =
                make_float2(acc[mi][ni][2] + b0, acc[mi][ni][3] + b1);
        }
    }
}

// ---------------------------------------------------------------------------
// Tensorized causal flash attention (bf16x3 QK and PV, FMA-pipe exp2).
//   CTA = 64 query rows, 128 threads (4 warps x 16 rows), 2 CTAs/SM.
//   R8 structure (KT=64, 2-stage) + deferred l-reduction (per-thread partial
//   sums through the rescale recurrence; one shuffle reduction at the end).
// smem: Q hi/lo 16KB @0; 2 stages x (Kh,Kl,Vh,Vl 8KB each) = 64KB @16KB.
// ---------------------------------------------------------------------------
#define KT 64
#define QROWS 64
#define ATTN_SMEM (16384 + 2 * 32768)   // 81920

__global__ __launch_bounds__(128, 2) void attn_mma(
    const __nv_bfloat16* __restrict__ Qh, const __nv_bfloat16* __restrict__ Ql,
    const __nv_bfloat16* __restrict__ Kh, const __nv_bfloat16* __restrict__ Kl,
    const __nv_bfloat16* __restrict__ Vh, const __nv_bfloat16* __restrict__ Vl,
    __nv_bfloat16* __restrict__ Ah, __nv_bfloat16* __restrict__ Al)
{
    extern __shared__ char smem[];
    const uint32_t sb = smem_u32(smem);
    const int tid = threadIdx.x, wid = tid >> 5, lid = tid & 31;
    const int qt = gridDim.x - 1 - blockIdx.x;   // heavy tiles first
    const int bh = blockIdx.y;
    const int qbase = qt * QROWS;
    const int ntiles = qt + 1;
    const size_t hbase = (size_t)bh * L_ * DK_;

    // ---- issue Q (group 0): 2 planes x 64 rows x 8 c16 = 1024 chunks ----
    {
        const __nv_bfloat16* qp[2] = { Qh + hbase + (size_t)qbase * DK_,
                                       Ql + hbase + (size_t)qbase * DK_ };
#pragma unroll
        for (int i = 0; i < 8; i++) {
            int id = tid + i * 128;
            int p = id >> 9, rem = id & 511;
            int r = rem >> 3, c16 = rem & 7;
            const __nv_bfloat16* src = qp[p] + (size_t)r * DK_ + c16 * 8;
            uint32_t dst = sb + (uint32_t)p * 8192u + (uint32_t)r * 128u +
                           (uint32_t)((c16 ^ (r & 7)) << 4);
            CP_ASYNC16(dst, src);
        }
        CP_COMMIT();
    }

    const __nv_bfloat16* kv[4] = { Kh + hbase, Kl + hbase, Vh + hbase, Vl + hbase };
#define ISSUE_STAGE(t) do {                                                  \
        int _kb = (t) * KT;                                                  \
        uint32_t _so = sb + 16384u + (uint32_t)((t) & 1) * 32768u;           \
        _Pragma("unroll")                                                    \
        for (int _i = 0; _i < 16; _i++) {                                    \
            int _id = tid + _i * 128;                                        \
            int _p = _id >> 9, _rem = _id & 511;                             \
            int _r = _rem >> 3, _c = _rem & 7;                               \
            const __nv_bfloat16* _s = kv[_p] + (size_t)(_kb + _r) * DK_ + _c * 8; \
            uint32_t _d = _so + (uint32_t)_p * 8192u + (uint32_t)_r * 128u + \
                          (uint32_t)((_c ^ (_r & 7)) << 4);                  \
            CP_ASYNC16(_d, _s);                                              \
        }                                                                    \
    } while (0)

    ISSUE_STAGE(0); CP_COMMIT();
    ISSUE_STAGE(1); CP_COMMIT();   // kb=64 always within [0, L)

    uint32_t qfh[4][4], qfl[4][4];
    float O[8][4];
#pragma unroll
    for (int i = 0; i < 8; i++)
#pragma unroll
        for (int j = 0; j < 4; j++) O[i][j] = 0.0f;
    float m0 = -1e30f, m1 = -1e30f;
    float l0p = 0.0f, l1p = 0.0f;     // per-thread partial row sums

    const int r0g = qbase + 16 * wid + (lid >> 2);
    const int wrow0 = qbase + 16 * wid;

    for (int t = 0; t < ntiles; t++) {
        CP_WAIT1();
        __syncthreads();
        const uint32_t so = sb + 16384u + (uint32_t)(t & 1) * 32768u;
        const int kb = t * KT;

        if (t == 0) {
#pragma unroll
            for (int kd = 0; kd < 4; kd++) {
                int row = 16 * wid + (lid & 15);
                int c16 = 2 * kd + (lid >> 4);
                uint32_t a = sb + (uint32_t)row * 128u + (uint32_t)((c16 ^ (row & 7)) << 4);
                ldm_x4(qfh[kd], a);
                ldm_x4(qfl[kd], a + 8192u);
            }
        }

        float S[8][4];
#pragma unroll
        for (int i = 0; i < 8; i++)
#pragma unroll
            for (int j = 0; j < 4; j++) S[i][j] = 0.0f;

#pragma unroll
        for (int kd = 0; kd < 4; kd++) {
#pragma unroll
            for (int p4 = 0; p4 < 4; p4++) {
                int row = p4 * 16 + (lid & 15);
                int c16 = 2 * kd + (lid >> 4);
                uint32_t a = so + (uint32_t)row * 128u + (uint32_t)((c16 ^ (row & 7)) << 4);
                uint32_t kh4[4], kl4[4];
                ldm_x4(kh4, a);
                ldm_x4(kl4, a + 8192u);
                uint32_t bh0[2] = { kh4[0], kh4[2] }, bh1[2] = { kh4[1], kh4[3] };
                uint32_t bl0[2] = { kl4[0], kl4[2] }, bl1[2] = { kl4[1], kl4[3] };
                mma_bf16(S[2 * p4], qfh[kd], bh0);
                mma_bf16(S[2 * p4], qfh[kd], bl0);
                mma_bf16(S[2 * p4], qfl[kd], bh0);
                mma_bf16(S[2 * p4 + 1], qfh[kd], bh1);
                mma_bf16(S[2 * p4 + 1], qfh[kd], bl1);
                mma_bf16(S[2 * p4 + 1], qfl[kd], bh1);
            }
        }

        if (kb + KT > wrow0) {
            int colb = kb + 2 * (lid & 3);
            int r1g = r0g + 8;
#pragma unroll
            for (int ni = 0; ni < 8; ni++) {
                int c = colb + 8 * ni;
                if (c > r0g)     S[ni][0] = -1e30f;
                if (c + 1 > r0g) S[ni][1] = -1e30f;
                if (c > r1g)     S[ni][2] = -1e30f;
                if (c + 1 > r1g) S[ni][3] = -1e30f;
            }
        }

        float t0 = -1e30f, t1 = -1e30f;
#pragma unroll
        for (int ni = 0; ni < 8; ni++) {
            t0 = fmaxf(t0, fmaxf(S[ni][0], S[ni][1]));
            t1 = fmaxf(t1, fmaxf(S[ni][2], S[ni][3]));
        }
        t0 = fmaxf(t0, __shfl_xor_sync(0xFFFFFFFFu, t0, 1));
        t0 = fmaxf(t0, __shfl_xor_sync(0xFFFFFFFFu, t0, 2));
        t1 = fmaxf(t1, __shfl_xor_sync(0xFFFFFFFFu, t1, 1));
        t1 = fmaxf(t1, __shfl_xor_sync(0xFFFFFFFFu, t1, 2));
        float n0 = fmaxf(m0, t0), n1 = fmaxf(m1, t1);
        float c0 = exp2p(m0 - n0), c1 = exp2p(m1 - n1);
        m0 = n0; m1 = n1;
        float s0 = 0.0f, s1 = 0.0f;
#pragma unroll
        for (int ni = 0; ni < 8; ni++) {
            S[ni][0] = exp2p(S[ni][0] - n0); s0 += S[ni][0];
            S[ni][1] = exp2p(S[ni][1] - n0); s0 += S[ni][1];
            S[ni][2] = exp2p(S[ni][2] - n1); s1 += S[ni][2];
            S[ni][3] = exp2p(S[ni][3] - n1); s1 += S[ni][3];
            O[ni][0] *= c0; O[ni][1] *= c0; O[ni][2] *= c1; O[ni][3] *= c1;
        }
        // deferred l: per-thread partials through the (row-uniform) rescale
        l0p = l0p * c0 + s0;
        l1p = l1p * c1 + s1;

        uint32_t ph[4][4], pl[4][4];
#pragma unroll
        for (int ks = 0; ks < 4; ks++) {
            split_pack(S[2 * ks][0], S[2 * ks][1], ph[ks][0], pl[ks][0]);
            split_pack(S[2 * ks][2], S[2 * ks][3], ph[ks][1], pl[ks][1]);
            split_pack(S[2 * ks + 1][0], S[2 * ks + 1][1], ph[ks][2], pl[ks][2]);
            split_pack(S[2 * ks + 1][2], S[2 * ks + 1][3], ph[ks][3], pl[ks][3]);
        }

#pragma unroll
        for (int ks = 0; ks < 4; ks++) {
#pragma unroll
            for (int jp = 0; jp < 4; jp++) {
                int row = ks * 16 + (lid & 15);
                int c16 = 2 * jp + (lid >> 4);
                uint32_t a = so + 16384u + (uint32_t)row * 128u +
                             (uint32_t)((c16 ^ (row & 7)) << 4);
                uint32_t vh4[4], vl4[4];
                ldm_x4t(vh4, a);
                ldm_x4t(vl4, a + 8192u);
                uint32_t bhe[2] = { vh4[0], vh4[1] }, bho[2] = { vh4[2], vh4[3] };
                uint32_t ble[2] = { vl4[0], vl4[1] }, blo[2] = { vl4[2], vl4[3] };
                mma_bf16(O[2 * jp], ph[ks], bhe);
                mma_bf16(O[2 * jp], ph[ks], ble);
                mma_bf16(O[2 * jp], pl[ks], bhe);
                mma_bf16(O[2 * jp + 1], ph[ks], bho);
                mma_bf16(O[2 * jp + 1], ph[ks], blo);
                mma_bf16(O[2 * jp + 1], pl[ks], bho);
            }
        }

        __syncthreads();
        if (t + 2 < ntiles) ISSUE_STAGE(t + 2);
        CP_COMMIT();
    }

    // final l reduction (once, not per tile)
    float l0 = l0p, l1 = l1p;
    l0 += __shfl_xor_sync(0xFFFFFFFFu, l0, 1);
    l0 += __shfl_xor_sync(0xFFFFFFFFu, l0, 2);
    l1 += __shfl_xor_sync(0xFFFFFFFFu, l1, 1);
    l1 += __shfl_xor_sync(0xFFFFFFFFu, l1, 2);

    float inv0 = 1.0f / l0, inv1 = 1.0f / l1;
    int b = bh >> 4, h = bh & (H_ - 1);
    size_t base0 = ((size_t)b * L_ + r0g) * D_ + h * DK_ + 2 * (lid & 3);
    size_t base1 = base0 + (size_t)8 * D_;
#pragma unroll
    for (int ni = 0; ni < 8; ni++) {
        uint32_t hp, lp;
        split_pack(O[ni][0] * inv0, O[ni][1] * inv0, hp, lp);
        *(uint32_t*)&Ah[base0 + 8 * ni] = hp;
        *(uint32_t*)&Al[base0 + 8 * ni] = lp;
        split_pack(O[ni][2] * inv1, O[ni][3] * inv1, hp, lp);
        *(uint32_t*)&Ah[base1 + 8 * ni] = hp;
        *(uint32_t*)&Al[base1 + 8 * ni] = lp;
    }
#undef ISSUE_STAGE
}

// ---------------------------------------------------------------------------
// Launch.  Inputs: query, key, value, mask, wq, bq, wk, bk, wv, bv, wo, bo
// ---------------------------------------------------------------------------
extern "C" void kernel_launch(void* const* d_in, const int* in_sizes, int n_in,
                              void* d_out, int out_size)
{
    (void)in_sizes; (void)n_in; (void)out_size;
    const float* query = (const float*)d_in[0];
    const float* key   = (const float*)d_in[1];
    const float* value = (const float*)d_in[2];
    const float* wq = (const float*)d_in[4];
    const float* bq = (const float*)d_in[5];
    const float* wk = (const float*)d_in[6];
    const float* bk = (const float*)d_in[7];
    const float* wv = (const float*)d_in[8];
    const float* bv = (const float*)d_in[9];
    const float* wo = (const float*)d_in[10];
    const float* bo = (const float*)d_in[11];

    __nv_bfloat16 *pQh, *pQl, *pKh, *pKl, *pVh, *pVl, *pWp, *pXp, *pAp;
    cudaGetSymbolAddress((void**)&pQh, g_Qh);
    cudaGetSymbolAddress((void**)&pQl, g_Ql);
    cudaGetSymbolAddress((void**)&pKh, g_KhP);
    cudaGetSymbolAddress((void**)&pKl, g_KlP);
    cudaGetSymbolAddress((void**)&pVh, g_VhP);
    cudaGetSymbolAddress((void**)&pVl, g_VlP);
    cudaGetSymbolAddress((void**)&pWp, g_Wp);
    cudaGetSymbolAddress((void**)&pXp, g_Xp);
    cudaGetSymbolAddress((void**)&pAp, g_Ap);

    cudaFuncSetAttribute(gemm_qkv, cudaFuncAttributeMaxDynamicSharedMemorySize, GEMM_SMEM);
    cudaFuncSetAttribute(gemm_out, cudaFuncAttributeMaxDynamicSharedMemorySize, GEMM_SMEM);
    cudaFuncSetAttribute(attn_mma, cudaFuncAttributeMaxDynamicSharedMemorySize, ATTN_SMEM);

    const size_t WSZ = (size_t)D_ * D_;
    const size_t XSZ = (size_t)M_ * D_;
    __nv_bfloat16 *w_hi[4], *w_lo[4], *x_hi[3], *x_lo[3];
    for (int i = 0; i < 4; i++) {
        w_hi[i] = pWp + (size_t)(2 * i) * WSZ;
        w_lo[i] = pWp + (size_t)(2 * i + 1) * WSZ;
    }
    for (int i = 0; i < 3; i++) {
        x_hi[i] = pXp + (size_t)(2 * i) * XSZ;
        x_lo[i] = pXp + (size_t)(2 * i + 1) * XSZ;
    }
    __nv_bfloat16* a_hi = pAp;
    __nv_bfloat16* a_lo = pAp + XSZ;

    // Fused splits: weights (z=4), inputs (z=3)
    {
        SplitArgs wa = {};
        const float* wsrc[4] = { wq, wk, wv, wo };
        for (int i = 0; i < 4; i++) {
            wa.src[i] = (const float4*)wsrc[i];
            wa.hi[i] = (uint32_t*)w_hi[i];
            wa.lo[i] = (uint32_t*)w_lo[i];
        }
        conv_split_multi<<<dim3(296, 1, 4), 256>>>(wa, (int)(WSZ / 4));

        SplitArgs xa = {};
        const float* xsrc[3] = { query, key, value };
        for (int i = 0; i < 3; i++) {
            xa.src[i] = (const float4*)xsrc[i];
            xa.hi[i] = (uint32_t*)x_hi[i];
            xa.lo[i] = (uint32_t*)x_lo[i];
        }
        conv_split_multi<<<dim3(394, 1, 3), 256>>>(xa, (int)(XSZ / 4));
    }

    // Merged QKV projection (grid.z = 3), 128x256 tiles
    {
        const float QSCALE = 0.18033688011112042f;   // log2(e) / sqrt(DK)
        QkvArgs qa = {};
        const float* biases[3] = { bq, bk, bv };
        __nv_bfloat16* ohs[3] = { pQh, pKh, pVh };
        __nv_bfloat16* ols[3] = { pQl, pKl, pVl };
        for (int i = 0; i < 3; i++) {
            qa.ah[i] = x_hi[i]; qa.al[i] = x_lo[i];
            qa.wh[i] = w_hi[i]; qa.wl[i] = w_lo[i];
            qa.bias[i] = biases[i];
            qa.oh[i] = ohs[i]; qa.ol[i] = ols[i];
            qa.scale[i] = (i == 0) ? QSCALE : 1.0f;
        }
        gemm_qkv<<<dim3(D_ / 256, M_ / 128, 3), 256, GEMM_SMEM>>>(qa);
    }

    dim3 agrid(L_ / QROWS, B_ * H_);   // (32, 32)
    attn_mma<<<agrid, 128, ATTN_SMEM>>>(pQh, pQl, pKh, pKl, pVh, pVl, a_hi, a_lo);

    gemm_out<<<dim3(D_ / 256, M_ / 128), 256, GEMM_SMEM>>>(
        a_hi, a_lo, w_hi[3], w_lo[3], bo, (float*)d_out);
}

// round 11
// speedup vs baseline: 1.1623x; 1.0878x over previous
#include <cuda_runtime.h>
#include <cuda_bf16.h>
#include <cuda_fp16.h>
#include <cstdint>
#include <math.h>

// Problem constants
#define B_  2
#define L_  2048
#define D_  1024
#define H_  16
#define DK_ 64
#define M_  (B_ * L_)   // 4096

// ---------------------------------------------------------------------------
// Scratch (device globals; no allocation allowed)
// ---------------------------------------------------------------------------
__device__ __nv_bfloat16 g_Qh[(size_t)M_ * D_];     // [B,H,L,DK] hi (scaled)
__device__ __nv_bfloat16 g_Ql[(size_t)M_ * D_];     // lo
__device__ __nv_bfloat16 g_KhP[(size_t)M_ * D_];
__device__ __nv_bfloat16 g_KlP[(size_t)M_ * D_];
__device__ __half        g_Vf[(size_t)M_ * D_];     // V single-plane fp16
__device__ __nv_bfloat16 g_Wp[4][2][(size_t)D_ * D_];   // weight hi/lo planes
__device__ __nv_bfloat16 g_Xp[3][2][(size_t)M_ * D_];   // q/k/v input hi/lo planes
__device__ __nv_bfloat16 g_Ap[2][(size_t)M_ * D_];      // attn-out hi/lo planes

// ---------------------------------------------------------------------------
// PTX helpers (base-ISA: ldmatrix / mma.sync / cp.async)
// ---------------------------------------------------------------------------
__device__ __forceinline__ uint32_t smem_u32(const void* p) {
    uint32_t a;
    asm("{ .reg .u64 t; cvta.to.shared.u64 t, %1; cvt.u32.u64 %0, t; }" : "=r"(a) : "l"(p));
    return a;
}

#define CP_ASYNC16(dst, src) \
    asm volatile("cp.async.cg.shared.global [%0], [%1], 16;" :: "r"(dst), "l"(src) : "memory")
#define CP_COMMIT() asm volatile("cp.async.commit_group;" ::: "memory")
#define CP_WAIT2()  asm volatile("cp.async.wait_group 2;" ::: "memory")
#define CP_WAIT1()  asm volatile("cp.async.wait_group 1;" ::: "memory")

__device__ __forceinline__ void ldm_x4(uint32_t* r, uint32_t addr) {
    asm volatile("ldmatrix.sync.aligned.m8n8.x4.shared.b16 {%0,%1,%2,%3}, [%4];"
                 : "=r"(r[0]), "=r"(r[1]), "=r"(r[2]), "=r"(r[3]) : "r"(addr));
}
__device__ __forceinline__ void ldm_x4t(uint32_t* r, uint32_t addr) {
    asm volatile("ldmatrix.sync.aligned.m8n8.x4.trans.shared.b16 {%0,%1,%2,%3}, [%4];"
                 : "=r"(r[0]), "=r"(r[1]), "=r"(r[2]), "=r"(r[3]) : "r"(addr));
}
__device__ __forceinline__ void mma_bf16(float* d, const uint32_t* a, const uint32_t* b) {
    asm volatile("mma.sync.aligned.m16n8k16.row.col.f32.bf16.bf16.f32 "
                 "{%0,%1,%2,%3}, {%4,%5,%6,%7}, {%8,%9}, {%0,%1,%2,%3};"
                 : "+f"(d[0]), "+f"(d[1]), "+f"(d[2]), "+f"(d[3])
                 : "r"(a[0]), "r"(a[1]), "r"(a[2]), "r"(a[3]), "r"(b[0]), "r"(b[1]));
}
__device__ __forceinline__ void mma_fp16(float* d, const uint32_t* a, const uint32_t* b) {
    asm volatile("mma.sync.aligned.m16n8k16.row.col.f32.f16.f16.f32 "
                 "{%0,%1,%2,%3}, {%4,%5,%6,%7}, {%8,%9}, {%0,%1,%2,%3};"
                 : "+f"(d[0]), "+f"(d[1]), "+f"(d[2]), "+f"(d[3])
                 : "r"(a[0]), "r"(a[1]), "r"(a[2]), "r"(a[3]), "r"(b[0]), "r"(b[1]));
}

// fast exp2 on FMA pipe, degree-3 poly: valid for t <= 0, clamps below -120.
__device__ __forceinline__ float exp2p(float t) {
    t = fmaxf(t, -120.0f);
    float r = t + 12582912.0f;          // 1.5 * 2^23: round-to-int in mantissa
    int sc = __float_as_int(r) << 23;   // integer part -> exponent field
    float f = t - (r - 12582912.0f);    // f in [-0.5, 0.5]
    float p = fmaf(f, 5.5504108665e-2f, 2.4022650696e-1f);
    p = fmaf(f, p, 6.9314718056e-1f);
    p = fmaf(f, p, 1.0f);
    return __int_as_float(__float_as_int(p) + sc);
}

// split pair (x0, x1) to bf16x2 hi and lo planes
__device__ __forceinline__ void split_pack(float x0, float x1, uint32_t& hp, uint32_t& lp) {
    asm("cvt.rn.bf16x2.f32 %0, %1, %2;" : "=r"(hp) : "f"(x1), "f"(x0));
    float e0 = x0 - __int_as_float((int)(hp << 16));
    float e1 = x1 - __int_as_float((int)(hp & 0xFFFF0000u));
    asm("cvt.rn.bf16x2.f32 %0, %1, %2;" : "=r"(lp) : "f"(e1), "f"(e0));
}
// pack (x0, x1) to f16x2 (x0 low, x1 high)
__device__ __forceinline__ uint32_t pack_f16x2(float x0, float x1) {
    uint32_t d;
    asm("cvt.rn.f16x2.f32 %0, %1, %2;" : "=r"(d) : "f"(x1), "f"(x0));
    return d;
}

// ---------------------------------------------------------------------------
// Fused fp32 -> (hi, lo) bf16 split: grid.z selects tensor
// ---------------------------------------------------------------------------
struct SplitArgs {
    const float4* src[4];
    uint32_t* hi[4];
    uint32_t* lo[4];
};

__global__ __launch_bounds__(256) void conv_split_multi(SplitArgs args, int n4)
{
    const int z = blockIdx.z;
    const float4* __restrict__ x = args.src[z];
    uint32_t* __restrict__ hi = args.hi[z];
    uint32_t* __restrict__ lo = args.lo[z];
    int i = blockIdx.x * blockDim.x + threadIdx.x;
    int stride = gridDim.x * blockDim.x;
    for (; i < n4; i += stride) {
        float4 v = x[i];
        uint32_t h0, l0h, h1, l1h;
        split_pack(v.x, v.y, h0, l0h);
        split_pack(v.z, v.w, h1, l1h);
        hi[2 * i] = h0; hi[2 * i + 1] = h1;
        lo[2 * i] = l0h; lo[2 * i + 1] = l1h;
    }
}

// ---------------------------------------------------------------------------
// bf16x3 GEMM tile core: 128(M) x 256(N) block, 8 warps (64x64 warp tiles),
// 3-stage cp.async pipeline. K-chunk 32. (unchanged from round 10)
// ---------------------------------------------------------------------------
#define NSTG      3
#define STG_BYTES 49152
#define BOFF_B    16384
#define GEMM_SMEM (NSTG * STG_BYTES)   // 147456
#define NKT       (D_ / 32)            // 32

__device__ __forceinline__ void gemm_issue_stage(
    uint32_t sb, const __nv_bfloat16* Ahi, const __nv_bfloat16* Alo,
    const __nv_bfloat16* Whi, const __nv_bfloat16* Wlo,
    int bm, int bn, int k0, int tid)
{
#pragma unroll
    for (int i = 0; i < 4; i++) {
        int id = tid + i * 256;
        int r = id >> 3, c16 = id & 7;
        int plane = c16 >> 2, kc = c16 & 3;
        const __nv_bfloat16* src = (plane ? Alo : Ahi) + (size_t)(bm + r) * D_ + k0 + kc * 8;
        uint32_t dst = sb + (uint32_t)r * 128u + (uint32_t)((c16 ^ (r & 7)) << 4);
        CP_ASYNC16(dst, src);
    }
#pragma unroll
    for (int i = 0; i < 8; i++) {
        int id = tid + i * 256;
        int plane = id >> 10, rem = id & 1023;
        int r = rem >> 5, c16 = rem & 31;
        const __nv_bfloat16* src = (plane ? Wlo : Whi) + (size_t)(k0 + r) * D_ + bn + c16 * 8;
        uint32_t dst = sb + BOFF_B + (uint32_t)plane * 16384u +
                       (uint32_t)r * 512u + (uint32_t)((c16 ^ (r & 7)) << 4);
        CP_ASYNC16(dst, src);
    }
}

__device__ __forceinline__ void gemm_mainloop(
    uint32_t sb0, const __nv_bfloat16* Ahi, const __nv_bfloat16* Alo,
    const __nv_bfloat16* Whi, const __nv_bfloat16* Wlo,
    int bm, int bn, int tid, int wm, int wn, int lid, float acc[4][8][4])
{
#pragma unroll
    for (int s = 0; s < 2; s++) {
        gemm_issue_stage(sb0 + s * STG_BYTES, Ahi, Alo, Whi, Wlo, bm, bn, s * 32, tid);
        CP_COMMIT();
    }

    uint32_t stg = 0;
    for (int kt = 0; kt < NKT; kt++) {
        CP_WAIT1();
        __syncthreads();
        const uint32_t sb = sb0 + stg * STG_BYTES;

#pragma unroll
        for (int ks = 0; ks < 2; ks++) {
            uint32_t af[4][2][4];
#pragma unroll
            for (int mi = 0; mi < 4; mi++)
#pragma unroll
                for (int p = 0; p < 2; p++) {
                    int m = wm + mi * 16 + (lid & 15);
                    int c16 = p * 4 + ks * 2 + (lid >> 4);
                    ldm_x4(af[mi][p], sb + (uint32_t)m * 128u + (uint32_t)((c16 ^ (m & 7)) << 4));
                }
            uint32_t bf[8][2][2];
#pragma unroll
            for (int nj = 0; nj < 4; nj++)
#pragma unroll
                for (int p = 0; p < 2; p++) {
                    int k = ks * 16 + (lid & 15);
                    int c16 = (wn >> 3) + 2 * nj + (lid >> 4);
                    uint32_t base = sb + BOFF_B + (uint32_t)p * 16384u;
                    uint32_t v4[4];
                    ldm_x4t(v4, base + (uint32_t)k * 512u + (uint32_t)((c16 ^ (k & 7)) << 4));
                    bf[2 * nj][p][0] = v4[0]; bf[2 * nj][p][1] = v4[1];
                    bf[2 * nj + 1][p][0] = v4[2]; bf[2 * nj + 1][p][1] = v4[3];
                }
#pragma unroll
            for (int mi = 0; mi < 4; mi++)
#pragma unroll
                for (int ni = 0; ni < 8; ni++) {
                    mma_bf16(acc[mi][ni], af[mi][0], bf[ni][0]);
                    mma_bf16(acc[mi][ni], af[mi][0], bf[ni][1]);
                    mma_bf16(acc[mi][ni], af[mi][1], bf[ni][0]);
                }
        }

        if (kt + 2 < NKT) {
            uint32_t nstg = stg + 2; if (nstg >= 3) nstg -= 3;
            gemm_issue_stage(sb0 + nstg * STG_BYTES,
                             Ahi, Alo, Whi, Wlo, bm, bn, (kt + 2) * 32, tid);
        }
        CP_COMMIT();
        if (++stg == 3) stg = 0;
    }
}

// ---------------------------------------------------------------------------
// Merged QKV projection GEMM: grid.z in {0:Q, 1:K, 2:V}
//   z 0/1: bf16 hi/lo planes out.  z 2: single fp16 plane out.
// ---------------------------------------------------------------------------
struct QkvArgs {
    const __nv_bfloat16* ah[3];
    const __nv_bfloat16* al[3];
    const __nv_bfloat16* wh[3];
    const __nv_bfloat16* wl[3];
    const float* bias[3];
    __nv_bfloat16* oh[3];
    __nv_bfloat16* ol[3];
    float scale[3];
};

__global__ __launch_bounds__(256, 1) void gemm_qkv(QkvArgs args)
{
    extern __shared__ char smem[];
    const uint32_t sb0 = smem_u32(smem);
    const int z = blockIdx.z;
    const int tid = threadIdx.x;
    const int wid = tid >> 5, lid = tid & 31;
    const int bm = blockIdx.y * 128, bn = blockIdx.x * 256;
    const int wm = (wid >> 2) * 64, wn = (wid & 3) * 64;

    float acc[4][8][4];
#pragma unroll
    for (int i = 0; i < 4; i++)
#pragma unroll
        for (int j = 0; j < 8; j++)
#pragma unroll
            for (int k = 0; k < 4; k++) acc[i][j][k] = 0.0f;

    gemm_mainloop(sb0, args.ah[z], args.al[z], args.wh[z], args.wl[z],
                  bm, bn, tid, wm, wn, lid, acc);

    const float* bias = args.bias[z];
    __nv_bfloat16* Pbh = args.oh[z];
    __nv_bfloat16* Pbl = args.ol[z];
    const float scale = args.scale[z];
    const bool vmode = (z == 2);
#pragma unroll
    for (int mi = 0; mi < 4; mi++) {
#pragma unroll
        for (int ni = 0; ni < 8; ni++) {
            int r0 = bm + wm + mi * 16 + (lid >> 2);
            int c0 = bn + wn + ni * 8 + (lid & 3) * 2;
            float b0 = __ldg(bias + c0), b1 = __ldg(bias + c0 + 1);
            float v0 = (acc[mi][ni][0] + b0) * scale, v1 = (acc[mi][ni][1] + b1) * scale;
            float v2 = (acc[mi][ni][2] + b0) * scale, v3 = (acc[mi][ni][3] + b1) * scale;
            int h = c0 >> 6, dk = c0 & 63, bb = r0 >> 11, ll = r0 & (L_ - 1);
            size_t base = ((size_t)(bb * H_ + h) * L_) * DK_ + dk;
            if (vmode) {
                *(uint32_t*)&Pbh[base + (size_t)ll * DK_] = pack_f16x2(v0, v1);
                *(uint32_t*)&Pbh[base + (size_t)(ll + 8) * DK_] = pack_f16x2(v2, v3);
            } else {
                uint32_t hp0, lp0, hp1, lp1;
                split_pack(v0, v1, hp0, lp0);
                split_pack(v2, v3, hp1, lp1);
                *(uint32_t*)&Pbh[base + (size_t)ll * DK_] = hp0;
                *(uint32_t*)&Pbh[base + (size_t)(ll + 8) * DK_] = hp1;
                *(uint32_t*)&Pbl[base + (size_t)ll * DK_] = lp0;
                *(uint32_t*)&Pbl[base + (size_t)(ll + 8) * DK_] = lp1;
            }
        }
    }
}

// ---------------------------------------------------------------------------
// Final projection GEMM: fp32 out [M,N]
// ---------------------------------------------------------------------------
__global__ __launch_bounds__(256, 1) void gemm_out(
    const __nv_bfloat16* __restrict__ Ahi, const __nv_bfloat16* __restrict__ Alo,
    const __nv_bfloat16* __restrict__ Whi, const __nv_bfloat16* __restrict__ Wlo,
    const float* __restrict__ bias, float* __restrict__ C)
{
    extern __shared__ char smem[];
    const uint32_t sb0 = smem_u32(smem);
    const int tid = threadIdx.x;
    const int wid = tid >> 5, lid = tid & 31;
    const int bm = blockIdx.y * 128, bn = blockIdx.x * 256;
    const int wm = (wid >> 2) * 64, wn = (wid & 3) * 64;

    float acc[4][8][4];
#pragma unroll
    for (int i = 0; i < 4; i++)
#pragma unroll
        for (int j = 0; j < 8; j++)
#pragma unroll
            for (int k = 0; k < 4; k++) acc[i][j][k] = 0.0f;

    gemm_mainloop(sb0, Ahi, Alo, Whi, Wlo, bm, bn, tid, wm, wn, lid, acc);

#pragma unroll
    for (int mi = 0; mi < 4; mi++) {
#pragma unroll
        for (int ni = 0; ni < 8; ni++) {
            int r0 = bm + wm + mi * 16 + (lid >> 2);
            int c0 = bn + wn + ni * 8 + (lid & 3) * 2;
            float b0 = __ldg(bias + c0), b1 = __ldg(bias + c0 + 1);
            *(float2*)(C + (size_t)r0 * D_ + c0) =
                make_float2(acc[mi][ni][0] + b0, acc[mi][ni][1] + b1);
            *(float2*)(C + (size_t)(r0 + 8) * D_ + c0) =
                make_float2(acc[mi][ni][2] + b0, acc[mi][ni][3] + b1);
        }
    }
}

// ---------------------------------------------------------------------------
// Tensorized causal flash attention.
//   QK: bf16x3.  PV: single-plane fp16 (P and V) -> 1/3 the PV mma + cheap packs.
//   CTA = 64 query rows, 128 threads (4 warps x 16 rows), 2 CTAs/SM.
//   Deferred l-reduction (one shuffle reduce in epilogue).
// smem: Q hi/lo 16KB @0; 2 stages x (Kh,Kl,Vf 8KB each = 24KB) @16KB. = 64KB
// ---------------------------------------------------------------------------
#define KT 64
#define QROWS 64
#define ASTG 24576
#define AVOFF 16384u                   // V offset within stage
#define ATTN_SMEM (16384 + 2 * ASTG)   // 65536

__global__ __launch_bounds__(128, 2) void attn_mma(
    const __nv_bfloat16* __restrict__ Qh, const __nv_bfloat16* __restrict__ Ql,
    const __nv_bfloat16* __restrict__ Kh, const __nv_bfloat16* __restrict__ Kl,
    const __half* __restrict__ Vf,
    __nv_bfloat16* __restrict__ Ah, __nv_bfloat16* __restrict__ Al)
{
    extern __shared__ char smem[];
    const uint32_t sb = smem_u32(smem);
    const int tid = threadIdx.x, wid = tid >> 5, lid = tid & 31;
    const int qt = gridDim.x - 1 - blockIdx.x;   // heavy tiles first
    const int bh = blockIdx.y;
    const int qbase = qt * QROWS;
    const int ntiles = qt + 1;
    const size_t hbase = (size_t)bh * L_ * DK_;

    // ---- issue Q (group 0): 2 planes x 64 rows x 8 c16 = 1024 chunks ----
    {
        const __nv_bfloat16* qp[2] = { Qh + hbase + (size_t)qbase * DK_,
                                       Ql + hbase + (size_t)qbase * DK_ };
#pragma unroll
        for (int i = 0; i < 8; i++) {
            int id = tid + i * 128;
            int p = id >> 9, rem = id & 511;
            int r = rem >> 3, c16 = rem & 7;
            const __nv_bfloat16* src = qp[p] + (size_t)r * DK_ + c16 * 8;
            uint32_t dst = sb + (uint32_t)p * 8192u + (uint32_t)r * 128u +
                           (uint32_t)((c16 ^ (r & 7)) << 4);
            CP_ASYNC16(dst, src);
        }
        CP_COMMIT();
    }

    // plane byte-pointers: rows of 128B each
    const char* kv[3] = { (const char*)(Kh + hbase), (const char*)(Kl + hbase),
                          (const char*)(Vf + hbase) };
#define ISSUE_STAGE(t) do {                                                  \
        int _kb = (t) * KT;                                                  \
        uint32_t _so = sb + 16384u + (uint32_t)((t) & 1) * ASTG;             \
        _Pragma("unroll")                                                    \
        for (int _i = 0; _i < 12; _i++) {                                    \
            int _id = tid + _i * 128;                                        \
            int _p = _id >> 9, _rem = _id & 511;                             \
            int _r = _rem >> 3, _c = _rem & 7;                               \
            const char* _s = kv[_p] + (size_t)(_kb + _r) * 128 + _c * 16;    \
            uint32_t _d = _so + (uint32_t)_p * 8192u + (uint32_t)_r * 128u + \
                          (uint32_t)((_c ^ (_r & 7)) << 4);                  \
            CP_ASYNC16(_d, _s);                                              \
        }                                                                    \
    } while (0)

    ISSUE_STAGE(0); CP_COMMIT();
    ISSUE_STAGE(1); CP_COMMIT();   // kb=64 always within [0, L)

    uint32_t qfh[4][4], qfl[4][4];
    float O[8][4];
#pragma unroll
    for (int i = 0; i < 8; i++)
#pragma unroll
        for (int j = 0; j < 4; j++) O[i][j] = 0.0f;
    float m0 = -1e30f, m1 = -1e30f;
    float l0p = 0.0f, l1p = 0.0f;     // per-thread partial row sums

    const int r0g = qbase + 16 * wid + (lid >> 2);
    const int wrow0 = qbase + 16 * wid;

    for (int t = 0; t < ntiles; t++) {
        CP_WAIT1();
        __syncthreads();
        const uint32_t so = sb + 16384u + (uint32_t)(t & 1) * ASTG;
        const int kb = t * KT;

        if (t == 0) {
#pragma unroll
            for (int kd = 0; kd < 4; kd++) {
                int row = 16 * wid + (lid & 15);
                int c16 = 2 * kd + (lid >> 4);
                uint32_t a = sb + (uint32_t)row * 128u + (uint32_t)((c16 ^ (row & 7)) << 4);
                ldm_x4(qfh[kd], a);
                ldm_x4(qfl[kd], a + 8192u);
            }
        }

        float S[8][4];
#pragma unroll
        for (int i = 0; i < 8; i++)
#pragma unroll
            for (int j = 0; j < 4; j++) S[i][j] = 0.0f;

#pragma unroll
        for (int kd = 0; kd < 4; kd++) {
#pragma unroll
            for (int p4 = 0; p4 < 4; p4++) {
                int row = p4 * 16 + (lid & 15);
                int c16 = 2 * kd + (lid >> 4);
                uint32_t a = so + (uint32_t)row * 128u + (uint32_t)((c16 ^ (row & 7)) << 4);
                uint32_t kh4[4], kl4[4];
                ldm_x4(kh4, a);
                ldm_x4(kl4, a + 8192u);
                uint32_t bh0[2] = { kh4[0], kh4[2] }, bh1[2] = { kh4[1], kh4[3] };
                uint32_t bl0[2] = { kl4[0], kl4[2] }, bl1[2] = { kl4[1], kl4[3] };
                mma_bf16(S[2 * p4], qfh[kd], bh0);
                mma_bf16(S[2 * p4], qfh[kd], bl0);
                mma_bf16(S[2 * p4], qfl[kd], bh0);
                mma_bf16(S[2 * p4 + 1], qfh[kd], bh1);
                mma_bf16(S[2 * p4 + 1], qfh[kd], bl1);
                mma_bf16(S[2 * p4 + 1], qfl[kd], bh1);
            }
        }

        if (kb + KT > wrow0) {
            int colb = kb + 2 * (lid & 3);
            int r1g = r0g + 8;
#pragma unroll
            for (int ni = 0; ni < 8; ni++) {
                int c = colb + 8 * ni;
                if (c > r0g)     S[ni][0] = -1e30f;
                if (c + 1 > r0g) S[ni][1] = -1e30f;
                if (c > r1g)     S[ni][2] = -1e30f;
                if (c + 1 > r1g) S[ni][3] = -1e30f;
            }
        }

        float t0 = -1e30f, t1 = -1e30f;
#pragma unroll
        for (int ni = 0; ni < 8; ni++) {
            t0 = fmaxf(t0, fmaxf(S[ni][0], S[ni][1]));
            t1 = fmaxf(t1, fmaxf(S[ni][2], S[ni][3]));
        }
        t0 = fmaxf(t0, __shfl_xor_sync(0xFFFFFFFFu, t0, 1));
        t0 = fmaxf(t0, __shfl_xor_sync(0xFFFFFFFFu, t0, 2));
        t1 = fmaxf(t1, __shfl_xor_sync(0xFFFFFFFFu, t1, 1));
        t1 = fmaxf(t1, __shfl_xor_sync(0xFFFFFFFFu, t1, 2));
        float n0 = fmaxf(m0, t0), n1 = fmaxf(m1, t1);
        float c0 = exp2p(m0 - n0), c1 = exp2p(m1 - n1);
        m0 = n0; m1 = n1;
        float s0 = 0.0f, s1 = 0.0f;
#pragma unroll
        for (int ni = 0; ni < 8; ni++) {
            S[ni][0] = exp2p(S[ni][0] - n0); s0 += S[ni][0];
            S[ni][1] = exp2p(S[ni][1] - n0); s0 += S[ni][1];
            S[ni][2] = exp2p(S[ni][2] - n1); s1 += S[ni][2];
            S[ni][3] = exp2p(S[ni][3] - n1); s1 += S[ni][3];
            O[ni][0] *= c0; O[ni][1] *= c0; O[ni][2] *= c1; O[ni][3] *= c1;
        }
        l0p = l0p * c0 + s0;
        l1p = l1p * c1 + s1;

        // ---- O += P V (fp16 single plane) ----
#pragma unroll
        for (int ks = 0; ks < 4; ks++) {
            uint32_t pf[4];
            pf[0] = pack_f16x2(S[2 * ks][0], S[2 * ks][1]);
            pf[1] = pack_f16x2(S[2 * ks][2], S[2 * ks][3]);
            pf[2] = pack_f16x2(S[2 * ks + 1][0], S[2 * ks + 1][1]);
            pf[3] = pack_f16x2(S[2 * ks + 1][2], S[2 * ks + 1][3]);
#pragma unroll
            for (int jp = 0; jp < 4; jp++) {
                int row = ks * 16 + (lid & 15);
                int c16 = 2 * jp + (lid >> 4);
                uint32_t a = so + AVOFF + (uint32_t)row * 128u +
                             (uint32_t)((c16 ^ (row & 7)) << 4);
                uint32_t vf4[4];
                ldm_x4t(vf4, a);
                uint32_t be[2] = { vf4[0], vf4[1] }, bo2[2] = { vf4[2], vf4[3] };
                mma_fp16(O[2 * jp], pf, be);
                mma_fp16(O[2 * jp + 1], pf, bo2);
            }
        }

        __syncthreads();
        if (t + 2 < ntiles) ISSUE_STAGE(t + 2);
        CP_COMMIT();
    }

    // final l reduction (once, not per tile)
    float l0 = l0p, l1 = l1p;
    l0 += __shfl_xor_sync(0xFFFFFFFFu, l0, 1);
    l0 += __shfl_xor_sync(0xFFFFFFFFu, l0, 2);
    l1 += __shfl_xor_sync(0xFFFFFFFFu, l1, 1);
    l1 += __shfl_xor_sync(0xFFFFFFFFu, l1, 2);

    float inv0 = 1.0f / l0, inv1 = 1.0f / l1;
    int b = bh >> 4, h = bh & (H_ - 1);
    size_t base0 = ((size_t)b * L_ + r0g) * D_ + h * DK_ + 2 * (lid & 3);
    size_t base1 = base0 + (size_t)8 * D_;
#pragma unroll
    for (int ni = 0; ni < 8; ni++) {
        uint32_t hp, lp;
        split_pack(O[ni][0] * inv0, O[ni][1] * inv0, hp, lp);
        *(uint32_t*)&Ah[base0 + 8 * ni] = hp;
        *(uint32_t*)&Al[base0 + 8 * ni] = lp;
        split_pack(O[ni][2] * inv1, O[ni][3] * inv1, hp, lp);
        *(uint32_t*)&Ah[base1 + 8 * ni] = hp;
        *(uint32_t*)&Al[base1 + 8 * ni] = lp;
    }
#undef ISSUE_STAGE
}

// ---------------------------------------------------------------------------
// Launch.  Inputs: query, key, value, mask, wq, bq, wk, bk, wv, bv, wo, bo
// ---------------------------------------------------------------------------
extern "C" void kernel_launch(void* const* d_in, const int* in_sizes, int n_in,
                              void* d_out, int out_size)
{
    (void)in_sizes; (void)n_in; (void)out_size;
    const float* query = (const float*)d_in[0];
    const float* key   = (const float*)d_in[1];
    const float* value = (const float*)d_in[2];
    const float* wq = (const float*)d_in[4];
    const float* bq = (const float*)d_in[5];
    const float* wk = (const float*)d_in[6];
    const float* bk = (const float*)d_in[7];
    const float* wv = (const float*)d_in[8];
    const float* bv = (const float*)d_in[9];
    const float* wo = (const float*)d_in[10];
    const float* bo = (const float*)d_in[11];

    __nv_bfloat16 *pQh, *pQl, *pKh, *pKl, *pWp, *pXp, *pAp;
    __half *pVf;
    cudaGetSymbolAddress((void**)&pQh, g_Qh);
    cudaGetSymbolAddress((void**)&pQl, g_Ql);
    cudaGetSymbolAddress((void**)&pKh, g_KhP);
    cudaGetSymbolAddress((void**)&pKl, g_KlP);
    cudaGetSymbolAddress((void**)&pVf, g_Vf);
    cudaGetSymbolAddress((void**)&pWp, g_Wp);
    cudaGetSymbolAddress((void**)&pXp, g_Xp);
    cudaGetSymbolAddress((void**)&pAp, g_Ap);

    cudaFuncSetAttribute(gemm_qkv, cudaFuncAttributeMaxDynamicSharedMemorySize, GEMM_SMEM);
    cudaFuncSetAttribute(gemm_out, cudaFuncAttributeMaxDynamicSharedMemorySize, GEMM_SMEM);
    cudaFuncSetAttribute(attn_mma, cudaFuncAttributeMaxDynamicSharedMemorySize, ATTN_SMEM);

    const size_t WSZ = (size_t)D_ * D_;
    const size_t XSZ = (size_t)M_ * D_;
    __nv_bfloat16 *w_hi[4], *w_lo[4], *x_hi[3], *x_lo[3];
    for (int i = 0; i < 4; i++) {
        w_hi[i] = pWp + (size_t)(2 * i) * WSZ;
        w_lo[i] = pWp + (size_t)(2 * i + 1) * WSZ;
    }
    for (int i = 0; i < 3; i++) {
        x_hi[i] = pXp + (size_t)(2 * i) * XSZ;
        x_lo[i] = pXp + (size_t)(2 * i + 1) * XSZ;
    }
    __nv_bfloat16* a_hi = pAp;
    __nv_bfloat16* a_lo = pAp + XSZ;

    // Fused splits: weights (z=4), inputs (z=3)
    {
        SplitArgs wa = {};
        const float* wsrc[4] = { wq, wk, wv, wo };
        for (int i = 0; i < 4; i++) {
            wa.src[i] = (const float4*)wsrc[i];
            wa.hi[i] = (uint32_t*)w_hi[i];
            wa.lo[i] = (uint32_t*)w_lo[i];
        }
        conv_split_multi<<<dim3(296, 1, 4), 256>>>(wa, (int)(WSZ / 4));

        SplitArgs xa = {};
        const float* xsrc[3] = { query, key, value };
        for (int i = 0; i < 3; i++) {
            xa.src[i] = (const float4*)xsrc[i];
            xa.hi[i] = (uint32_t*)x_hi[i];
            xa.lo[i] = (uint32_t*)x_lo[i];
        }
        conv_split_multi<<<dim3(394, 1, 3), 256>>>(xa, (int)(XSZ / 4));
    }

    // Merged QKV projection (grid.z = 3), 128x256 tiles
    {
        const float QSCALE = 0.18033688011112042f;   // log2(e) / sqrt(DK)
        QkvArgs qa = {};
        const float* biases[3] = { bq, bk, bv };
        __nv_bfloat16* ohs[3] = { pQh, pKh, (__nv_bfloat16*)pVf };
        __nv_bfloat16* ols[3] = { pQl, pKl, nullptr };
        for (int i = 0; i < 3; i++) {
            qa.ah[i] = x_hi[i]; qa.al[i] = x_lo[i];
            qa.wh[i] = w_hi[i]; qa.wl[i] = w_lo[i];
            qa.bias[i] = biases[i];
            qa.oh[i] = ohs[i]; qa.ol[i] = ols[i];
            qa.scale[i] = (i == 0) ? QSCALE : 1.0f;
        }
        gemm_qkv<<<dim3(D_ / 256, M_ / 128, 3), 256, GEMM_SMEM>>>(qa);
    }

    dim3 agrid(L_ / QROWS, B_ * H_);   // (32, 32)
    attn_mma<<<agrid, 128, ATTN_SMEM>>>(pQh, pQl, pKh, pKl, pVf, a_hi, a_lo);

    gemm_out<<<dim3(D_ / 256, M_ / 128), 256, GEMM_SMEM>>>(
        a_hi, a_lo, w_hi[3], w_lo[3], bo, (float*)d_out);
}

// round 12
// speedup vs baseline: 1.4097x; 1.2129x over previous
#include <cuda_runtime.h>
#include <cuda_bf16.h>
#include <cuda_fp16.h>
#include <cstdint>
#include <math.h>

// Problem constants
#define B_  2
#define L_  2048
#define D_  1024
#define H_  16
#define DK_ 64
#define M_  (B_ * L_)   // 4096

// ---------------------------------------------------------------------------
// Scratch (device globals; no allocation allowed)
// ---------------------------------------------------------------------------
__device__ __nv_bfloat16 g_Qh[(size_t)M_ * D_];     // [B,H,L,DK] hi (scaled)
__device__ __nv_bfloat16 g_Ql[(size_t)M_ * D_];     // lo
__device__ __nv_bfloat16 g_KhP[(size_t)M_ * D_];
__device__ __nv_bfloat16 g_KlP[(size_t)M_ * D_];
__device__ __half        g_Vf[(size_t)M_ * D_];     // V single-plane fp16
__device__ __half        g_Wf[4][2][(size_t)D_ * D_];   // weight fp16 hi/lo planes
__device__ __half        g_Xf[3][(size_t)M_ * D_];      // inputs, single fp16 plane
__device__ __half        g_Af[(size_t)M_ * D_];         // attn-out, single fp16 plane

// ---------------------------------------------------------------------------
// PTX helpers (base-ISA: ldmatrix / mma.sync / cp.async)
// ---------------------------------------------------------------------------
__device__ __forceinline__ uint32_t smem_u32(const void* p) {
    uint32_t a;
    asm("{ .reg .u64 t; cvta.to.shared.u64 t, %1; cvt.u32.u64 %0, t; }" : "=r"(a) : "l"(p));
    return a;
}

#define CP_ASYNC16(dst, src) \
    asm volatile("cp.async.cg.shared.global [%0], [%1], 16;" :: "r"(dst), "l"(src) : "memory")
#define CP_COMMIT() asm volatile("cp.async.commit_group;" ::: "memory")
#define CP_WAIT1()  asm volatile("cp.async.wait_group 1;" ::: "memory")

__device__ __forceinline__ void ldm_x4(uint32_t* r, uint32_t addr) {
    asm volatile("ldmatrix.sync.aligned.m8n8.x4.shared.b16 {%0,%1,%2,%3}, [%4];"
                 : "=r"(r[0]), "=r"(r[1]), "=r"(r[2]), "=r"(r[3]) : "r"(addr));
}
__device__ __forceinline__ void ldm_x4t(uint32_t* r, uint32_t addr) {
    asm volatile("ldmatrix.sync.aligned.m8n8.x4.trans.shared.b16 {%0,%1,%2,%3}, [%4];"
                 : "=r"(r[0]), "=r"(r[1]), "=r"(r[2]), "=r"(r[3]) : "r"(addr));
}
__device__ __forceinline__ void mma_bf16(float* d, const uint32_t* a, const uint32_t* b) {
    asm volatile("mma.sync.aligned.m16n8k16.row.col.f32.bf16.bf16.f32 "
                 "{%0,%1,%2,%3}, {%4,%5,%6,%7}, {%8,%9}, {%0,%1,%2,%3};"
                 : "+f"(d[0]), "+f"(d[1]), "+f"(d[2]), "+f"(d[3])
                 : "r"(a[0]), "r"(a[1]), "r"(a[2]), "r"(a[3]), "r"(b[0]), "r"(b[1]));
}
__device__ __forceinline__ void mma_fp16(float* d, const uint32_t* a, const uint32_t* b) {
    asm volatile("mma.sync.aligned.m16n8k16.row.col.f32.f16.f16.f32 "
                 "{%0,%1,%2,%3}, {%4,%5,%6,%7}, {%8,%9}, {%0,%1,%2,%3};"
                 : "+f"(d[0]), "+f"(d[1]), "+f"(d[2]), "+f"(d[3])
                 : "r"(a[0]), "r"(a[1]), "r"(a[2]), "r"(a[3]), "r"(b[0]), "r"(b[1]));
}

// fast exp2 on FMA pipe, degree-3 poly: valid for t <= 0, clamps below -120.
__device__ __forceinline__ float exp2p(float t) {
    t = fmaxf(t, -120.0f);
    float r = t + 12582912.0f;
    int sc = __float_as_int(r) << 23;
    float f = t - (r - 12582912.0f);
    float p = fmaf(f, 5.5504108665e-2f, 2.4022650696e-1f);
    p = fmaf(f, p, 6.9314718056e-1f);
    p = fmaf(f, p, 1.0f);
    return __int_as_float(__float_as_int(p) + sc);
}

// split pair (x0, x1) to bf16x2 hi and lo planes
__device__ __forceinline__ void split_pack(float x0, float x1, uint32_t& hp, uint32_t& lp) {
    asm("cvt.rn.bf16x2.f32 %0, %1, %2;" : "=r"(hp) : "f"(x1), "f"(x0));
    float e0 = x0 - __int_as_float((int)(hp << 16));
    float e1 = x1 - __int_as_float((int)(hp & 0xFFFF0000u));
    asm("cvt.rn.bf16x2.f32 %0, %1, %2;" : "=r"(lp) : "f"(e1), "f"(e0));
}
// pack (x0, x1) to f16x2 (x0 low, x1 high)
__device__ __forceinline__ uint32_t pack_f16x2(float x0, float x1) {
    uint32_t d;
    asm("cvt.rn.f16x2.f32 %0, %1, %2;" : "=r"(d) : "f"(x1), "f"(x0));
    return d;
}
// split pair to fp16 hi/lo planes
__device__ __forceinline__ void split_pack_f16(float x0, float x1, uint32_t& hp, uint32_t& lp) {
    hp = pack_f16x2(x0, x1);
    float2 back = __half22float2(*(__half2*)&hp);
    lp = pack_f16x2(x0 - back.x, x1 - back.y);
}

// ---------------------------------------------------------------------------
// Weight split: fp32 -> fp16 hi/lo planes (grid.z = 4)
// ---------------------------------------------------------------------------
struct WSplitArgs {
    const float4* src[4];
    uint32_t* hi[4];
    uint32_t* lo[4];
};
__global__ __launch_bounds__(256) void conv_w_f16(WSplitArgs args, int n4)
{
    const int z = blockIdx.z;
    const float4* __restrict__ x = args.src[z];
    uint32_t* __restrict__ hi = args.hi[z];
    uint32_t* __restrict__ lo = args.lo[z];
    int i = blockIdx.x * blockDim.x + threadIdx.x;
    int stride = gridDim.x * blockDim.x;
    for (; i < n4; i += stride) {
        float4 v = x[i];
        uint32_t h0, l0, h1, l1;
        split_pack_f16(v.x, v.y, h0, l0);
        split_pack_f16(v.z, v.w, h1, l1);
        hi[2 * i] = h0; hi[2 * i + 1] = h1;
        lo[2 * i] = l0; lo[2 * i + 1] = l1;
    }
}

// ---------------------------------------------------------------------------
// Input convert: fp32 -> fp16 single plane (grid.z = 3)
// ---------------------------------------------------------------------------
struct XConvArgs {
    const float4* src[3];
    uint32_t* dst[3];
};
__global__ __launch_bounds__(256) void conv_x_f16(XConvArgs args, int n4)
{
    const int z = blockIdx.z;
    const float4* __restrict__ x = args.src[z];
    uint32_t* __restrict__ d = args.dst[z];
    int i = blockIdx.x * blockDim.x + threadIdx.x;
    int stride = gridDim.x * blockDim.x;
    for (; i < n4; i += stride) {
        float4 v = x[i];
        d[2 * i]     = pack_f16x2(v.x, v.y);
        d[2 * i + 1] = pack_f16x2(v.z, v.w);
    }
}

// ---------------------------------------------------------------------------
// fp16x2 GEMM tile core: C = A[M,K] @ W[K,N], A single fp16 plane, W hi/lo.
// 128(M) x 256(N) block, 8 warps (64x64 warp tiles), 3-stage cp.async, kt=32.
// Stage: A 8KB (two M-rows of 64B packed per 128B smem row, XOR-swizzled),
//        B 32KB (2 planes x 32 k-rows x 512B).   2 mma per (mi,ni,ks).
// ---------------------------------------------------------------------------
#define STG_BYTES 40960
#define BOFF_B    8192
#define GEMM_SMEM (3 * STG_BYTES)      // 122880
#define NKT       (D_ / 32)            // 32

// byte offset of (m-row, c16 chunk 0..3) within the packed A tile
__device__ __forceinline__ uint32_t abyte(int m, int c) {
    return (uint32_t)(m >> 1) * 128u +
           (uint32_t)((((m & 1) * 4 + c) ^ ((m >> 1) & 7)) << 4);
}

__device__ __forceinline__ void gemm_issue_stage(
    uint32_t sb, const __half* Af16, const __half* Wh, const __half* Wl,
    int bm, int bn, int k0, int tid)
{
    // A tile: 128 rows x 4 c16 = 512 chunks
#pragma unroll
    for (int i = 0; i < 2; i++) {
        int id = tid + i * 256;
        int r = id >> 2, c = id & 3;
        const __half* src = Af16 + (size_t)(bm + r) * D_ + k0 + c * 8;
        CP_ASYNC16(sb + abyte(r, c), src);
    }
    // B tile: 2 planes x 32 k-rows x 32 c16 = 2048 chunks
#pragma unroll
    for (int i = 0; i < 8; i++) {
        int id = tid + i * 256;
        int plane = id >> 10, rem = id & 1023;
        int r = rem >> 5, c32 = rem & 31;
        const __half* src = (plane ? Wl : Wh) + (size_t)(k0 + r) * D_ + bn + c32 * 8;
        uint32_t dst = sb + BOFF_B + (uint32_t)plane * 16384u +
                       (uint32_t)r * 512u + (uint32_t)((c32 ^ (r & 7)) << 4);
        CP_ASYNC16(dst, src);
    }
}

__device__ __forceinline__ void gemm_mainloop(
    uint32_t sb0, const __half* Af16, const __half* Wh, const __half* Wl,
    int bm, int bn, int tid, int wm, int wn, int lid, float acc[4][8][4])
{
#pragma unroll
    for (int s = 0; s < 2; s++) {
        gemm_issue_stage(sb0 + s * STG_BYTES, Af16, Wh, Wl, bm, bn, s * 32, tid);
        CP_COMMIT();
    }

    uint32_t stg = 0;
    for (int kt = 0; kt < NKT; kt++) {
        CP_WAIT1();
        __syncthreads();
        const uint32_t sb = sb0 + stg * STG_BYTES;

#pragma unroll
        for (int ks = 0; ks < 2; ks++) {
            uint32_t af[4][4];
#pragma unroll
            for (int mi = 0; mi < 4; mi++) {
                int m = wm + mi * 16 + (lid & 15);
                int c = ks * 2 + (lid >> 4);
                ldm_x4(af[mi], sb + abyte(m, c));
            }
            uint32_t bf[8][2][2];
#pragma unroll
            for (int nj = 0; nj < 4; nj++)
#pragma unroll
                for (int p = 0; p < 2; p++) {
                    int k = ks * 16 + (lid & 15);
                    int c32 = (wn >> 3) + 2 * nj + (lid >> 4);
                    uint32_t base = sb + BOFF_B + (uint32_t)p * 16384u;
                    uint32_t v4[4];
                    ldm_x4t(v4, base + (uint32_t)k * 512u + (uint32_t)((c32 ^ (k & 7)) << 4));
                    bf[2 * nj][p][0] = v4[0]; bf[2 * nj][p][1] = v4[1];
                    bf[2 * nj + 1][p][0] = v4[2]; bf[2 * nj + 1][p][1] = v4[3];
                }
#pragma unroll
            for (int mi = 0; mi < 4; mi++)
#pragma unroll
                for (int ni = 0; ni < 8; ni++) {
                    mma_fp16(acc[mi][ni], af[mi], bf[ni][0]);
                    mma_fp16(acc[mi][ni], af[mi], bf[ni][1]);
                }
        }

        if (kt + 2 < NKT) {
            uint32_t nstg = stg + 2; if (nstg >= 3) nstg -= 3;
            gemm_issue_stage(sb0 + nstg * STG_BYTES,
                             Af16, Wh, Wl, bm, bn, (kt + 2) * 32, tid);
        }
        CP_COMMIT();
        if (++stg == 3) stg = 0;
    }
}

// ---------------------------------------------------------------------------
// Merged QKV projection GEMM: grid.z in {0:Q, 1:K, 2:V}
//   z 0/1: bf16 hi/lo planes out.  z 2: single fp16 plane out.
// ---------------------------------------------------------------------------
struct QkvArgs {
    const __half* a[3];
    const __half* wh[3];
    const __half* wl[3];
    const float* bias[3];
    __nv_bfloat16* oh[3];
    __nv_bfloat16* ol[3];
    float scale[3];
};

__global__ __launch_bounds__(256, 1) void gemm_qkv(QkvArgs args)
{
    extern __shared__ char smem[];
    const uint32_t sb0 = smem_u32(smem);
    const int z = blockIdx.z;
    const int tid = threadIdx.x;
    const int wid = tid >> 5, lid = tid & 31;
    const int bm = blockIdx.y * 128, bn = blockIdx.x * 256;
    const int wm = (wid >> 2) * 64, wn = (wid & 3) * 64;

    float acc[4][8][4];
#pragma unroll
    for (int i = 0; i < 4; i++)
#pragma unroll
        for (int j = 0; j < 8; j++)
#pragma unroll
            for (int k = 0; k < 4; k++) acc[i][j][k] = 0.0f;

    gemm_mainloop(sb0, args.a[z], args.wh[z], args.wl[z], bm, bn, tid, wm, wn, lid, acc);

    const float* bias = args.bias[z];
    __nv_bfloat16* Pbh = args.oh[z];
    __nv_bfloat16* Pbl = args.ol[z];
    const float scale = args.scale[z];
    const bool vmode = (z == 2);
#pragma unroll
    for (int mi = 0; mi < 4; mi++) {
#pragma unroll
        for (int ni = 0; ni < 8; ni++) {
            int r0 = bm + wm + mi * 16 + (lid >> 2);
            int c0 = bn + wn + ni * 8 + (lid & 3) * 2;
            float b0 = __ldg(bias + c0), b1 = __ldg(bias + c0 + 1);
            float v0 = (acc[mi][ni][0] + b0) * scale, v1 = (acc[mi][ni][1] + b1) * scale;
            float v2 = (acc[mi][ni][2] + b0) * scale, v3 = (acc[mi][ni][3] + b1) * scale;
            int h = c0 >> 6, dk = c0 & 63, bb = r0 >> 11, ll = r0 & (L_ - 1);
            size_t base = ((size_t)(bb * H_ + h) * L_) * DK_ + dk;
            if (vmode) {
                *(uint32_t*)&Pbh[base + (size_t)ll * DK_] = pack_f16x2(v0, v1);
                *(uint32_t*)&Pbh[base + (size_t)(ll + 8) * DK_] = pack_f16x2(v2, v3);
            } else {
                uint32_t hp0, lp0, hp1, lp1;
                split_pack(v0, v1, hp0, lp0);
                split_pack(v2, v3, hp1, lp1);
                *(uint32_t*)&Pbh[base + (size_t)ll * DK_] = hp0;
                *(uint32_t*)&Pbh[base + (size_t)(ll + 8) * DK_] = hp1;
                *(uint32_t*)&Pbl[base + (size_t)ll * DK_] = lp0;
                *(uint32_t*)&Pbl[base + (size_t)(ll + 8) * DK_] = lp1;
            }
        }
    }
}

// ---------------------------------------------------------------------------
// Final projection GEMM: fp32 out [M,N]
// ---------------------------------------------------------------------------
__global__ __launch_bounds__(256, 1) void gemm_out(
    const __half* __restrict__ Af16,
    const __half* __restrict__ Wh, const __half* __restrict__ Wl,
    const float* __restrict__ bias, float* __restrict__ C)
{
    extern __shared__ char smem[];
    const uint32_t sb0 = smem_u32(smem);
    const int tid = threadIdx.x;
    const int wid = tid >> 5, lid = tid & 31;
    const int bm = blockIdx.y * 128, bn = blockIdx.x * 256;
    const int wm = (wid >> 2) * 64, wn = (wid & 3) * 64;

    float acc[4][8][4];
#pragma unroll
    for (int i = 0; i < 4; i++)
#pragma unroll
        for (int j = 0; j < 8; j++)
#pragma unroll
            for (int k = 0; k < 4; k++) acc[i][j][k] = 0.0f;

    gemm_mainloop(sb0, Af16, Wh, Wl, bm, bn, tid, wm, wn, lid, acc);

#pragma unroll
    for (int mi = 0; mi < 4; mi++) {
#pragma unroll
        for (int ni = 0; ni < 8; ni++) {
            int r0 = bm + wm + mi * 16 + (lid >> 2);
            int c0 = bn + wn + ni * 8 + (lid & 3) * 2;
            float b0 = __ldg(bias + c0), b1 = __ldg(bias + c0 + 1);
            *(float2*)(C + (size_t)r0 * D_ + c0) =
                make_float2(acc[mi][ni][0] + b0, acc[mi][ni][1] + b1);
            *(float2*)(C + (size_t)(r0 + 8) * D_ + c0) =
                make_float2(acc[mi][ni][2] + b0, acc[mi][ni][3] + b1);
        }
    }
}

// ---------------------------------------------------------------------------
// Tensorized causal flash attention.
//   QK: bf16x3.  PV: single-plane fp16.  Output: single fp16 plane.
//   CTA = 64 query rows, 128 threads (4 warps x 16 rows), 2 CTAs/SM.
// smem: Q hi/lo 16KB @0; 2 stages x (Kh,Kl,Vf 8KB each = 24KB) @16KB. = 64KB
// ---------------------------------------------------------------------------
#define KT 64
#define QROWS 64
#define ASTG 24576
#define AVOFF 16384u
#define ATTN_SMEM (16384 + 2 * ASTG)   // 65536

__global__ __launch_bounds__(128, 2) void attn_mma(
    const __nv_bfloat16* __restrict__ Qh, const __nv_bfloat16* __restrict__ Ql,
    const __nv_bfloat16* __restrict__ Kh, const __nv_bfloat16* __restrict__ Kl,
    const __half* __restrict__ Vf, __half* __restrict__ Af)
{
    extern __shared__ char smem[];
    const uint32_t sb = smem_u32(smem);
    const int tid = threadIdx.x, wid = tid >> 5, lid = tid & 31;
    const int qt = gridDim.x - 1 - blockIdx.x;   // heavy tiles first
    const int bh = blockIdx.y;
    const int qbase = qt * QROWS;
    const int ntiles = qt + 1;
    const size_t hbase = (size_t)bh * L_ * DK_;

    // ---- issue Q (group 0): 2 planes x 64 rows x 8 c16 = 1024 chunks ----
    {
        const __nv_bfloat16* qp[2] = { Qh + hbase + (size_t)qbase * DK_,
                                       Ql + hbase + (size_t)qbase * DK_ };
#pragma unroll
        for (int i = 0; i < 8; i++) {
            int id = tid + i * 128;
            int p = id >> 9, rem = id & 511;
            int r = rem >> 3, c16 = rem & 7;
            const __nv_bfloat16* src = qp[p] + (size_t)r * DK_ + c16 * 8;
            uint32_t dst = sb + (uint32_t)p * 8192u + (uint32_t)r * 128u +
                           (uint32_t)((c16 ^ (r & 7)) << 4);
            CP_ASYNC16(dst, src);
        }
        CP_COMMIT();
    }

    const char* kv[3] = { (const char*)(Kh + hbase), (const char*)(Kl + hbase),
                          (const char*)(Vf + hbase) };
#define ISSUE_STAGE(t) do {                                                  \
        int _kb = (t) * KT;                                                  \
        uint32_t _so = sb + 16384u + (uint32_t)((t) & 1) * ASTG;             \
        _Pragma("unroll")                                                    \
        for (int _i = 0; _i < 12; _i++) {                                    \
            int _id = tid + _i * 128;                                        \
            int _p = _id >> 9, _rem = _id & 511;                             \
            int _r = _rem >> 3, _c = _rem & 7;                               \
            const char* _s = kv[_p] + (size_t)(_kb + _r) * 128 + _c * 16;    \
            uint32_t _d = _so + (uint32_t)_p * 8192u + (uint32_t)_r * 128u + \
                          (uint32_t)((_c ^ (_r & 7)) << 4);                  \
            CP_ASYNC16(_d, _s);                                              \
        }                                                                    \
    } while (0)

    ISSUE_STAGE(0); CP_COMMIT();
    ISSUE_STAGE(1); CP_COMMIT();

    uint32_t qfh[4][4], qfl[4][4];
    float O[8][4];
#pragma unroll
    for (int i = 0; i < 8; i++)
#pragma unroll
        for (int j = 0; j < 4; j++) O[i][j] = 0.0f;
    float m0 = -1e30f, m1 = -1e30f;
    float l0p = 0.0f, l1p = 0.0f;

    const int r0g = qbase + 16 * wid + (lid >> 2);
    const int wrow0 = qbase + 16 * wid;

    for (int t = 0; t < ntiles; t++) {
        CP_WAIT1();
        __syncthreads();
        const uint32_t so = sb + 16384u + (uint32_t)(t & 1) * ASTG;
        const int kb = t * KT;

        if (t == 0) {
#pragma unroll
            for (int kd = 0; kd < 4; kd++) {
                int row = 16 * wid + (lid & 15);
                int c16 = 2 * kd + (lid >> 4);
                uint32_t a = sb + (uint32_t)row * 128u + (uint32_t)((c16 ^ (row & 7)) << 4);
                ldm_x4(qfh[kd], a);
                ldm_x4(qfl[kd], a + 8192u);
            }
        }

        float S[8][4];
#pragma unroll
        for (int i = 0; i < 8; i++)
#pragma unroll
            for (int j = 0; j < 4; j++) S[i][j] = 0.0f;

#pragma unroll
        for (int kd = 0; kd < 4; kd++) {
#pragma unroll
            for (int p4 = 0; p4 < 4; p4++) {
                int row = p4 * 16 + (lid & 15);
                int c16 = 2 * kd + (lid >> 4);
                uint32_t a = so + (uint32_t)row * 128u + (uint32_t)((c16 ^ (row & 7)) << 4);
                uint32_t kh4[4], kl4[4];
                ldm_x4(kh4, a);
                ldm_x4(kl4, a + 8192u);
                uint32_t bh0[2] = { kh4[0], kh4[2] }, bh1[2] = { kh4[1], kh4[3] };
                uint32_t bl0[2] = { kl4[0], kl4[2] }, bl1[2] = { kl4[1], kl4[3] };
                mma_bf16(S[2 * p4], qfh[kd], bh0);
                mma_bf16(S[2 * p4], qfh[kd], bl0);
                mma_bf16(S[2 * p4], qfl[kd], bh0);
                mma_bf16(S[2 * p4 + 1], qfh[kd], bh1);
                mma_bf16(S[2 * p4 + 1], qfh[kd], bl1);
                mma_bf16(S[2 * p4 + 1], qfl[kd], bh1);
            }
        }

        if (kb + KT > wrow0) {
            int colb = kb + 2 * (lid & 3);
            int r1g = r0g + 8;
#pragma unroll
            for (int ni = 0; ni < 8; ni++) {
                int c = colb + 8 * ni;
                if (c > r0g)     S[ni][0] = -1e30f;
                if (c + 1 > r0g) S[ni][1] = -1e30f;
                if (c > r1g)     S[ni][2] = -1e30f;
                if (c + 1 > r1g) S[ni][3] = -1e30f;
            }
        }

        float t0 = -1e30f, t1 = -1e30f;
#pragma unroll
        for (int ni = 0; ni < 8; ni++) {
            t0 = fmaxf(t0, fmaxf(S[ni][0], S[ni][1]));
            t1 = fmaxf(t1, fmaxf(S[ni][2], S[ni][3]));
        }
        t0 = fmaxf(t0, __shfl_xor_sync(0xFFFFFFFFu, t0, 1));
        t0 = fmaxf(t0, __shfl_xor_sync(0xFFFFFFFFu, t0, 2));
        t1 = fmaxf(t1, __shfl_xor_sync(0xFFFFFFFFu, t1, 1));
        t1 = fmaxf(t1, __shfl_xor_sync(0xFFFFFFFFu, t1, 2));
        float n0 = fmaxf(m0, t0), n1 = fmaxf(m1, t1);
        float c0 = exp2p(m0 - n0), c1 = exp2p(m1 - n1);
        m0 = n0; m1 = n1;
        float s0 = 0.0f, s1 = 0.0f;
#pragma unroll
        for (int ni = 0; ni < 8; ni++) {
            S[ni][0] = exp2p(S[ni][0] - n0); s0 += S[ni][0];
            S[ni][1] = exp2p(S[ni][1] - n0); s0 += S[ni][1];
            S[ni][2] = exp2p(S[ni][2] - n1); s1 += S[ni][2];
            S[ni][3] = exp2p(S[ni][3] - n1); s1 += S[ni][3];
            O[ni][0] *= c0; O[ni][1] *= c0; O[ni][2] *= c1; O[ni][3] *= c1;
        }
        l0p = l0p * c0 + s0;
        l1p = l1p * c1 + s1;

        // ---- O += P V (fp16 single plane) ----
#pragma unroll
        for (int ks = 0; ks < 4; ks++) {
            uint32_t pf[4];
            pf[0] = pack_f16x2(S[2 * ks][0], S[2 * ks][1]);
            pf[1] = pack_f16x2(S[2 * ks][2], S[2 * ks][3]);
            pf[2] = pack_f16x2(S[2 * ks + 1][0], S[2 * ks + 1][1]);
            pf[3] = pack_f16x2(S[2 * ks + 1][2], S[2 * ks + 1][3]);
#pragma unroll
            for (int jp = 0; jp < 4; jp++) {
                int row = ks * 16 + (lid & 15);
                int c16 = 2 * jp + (lid >> 4);
                uint32_t a = so + AVOFF + (uint32_t)row * 128u +
                             (uint32_t)((c16 ^ (row & 7)) << 4);
                uint32_t vf4[4];
                ldm_x4t(vf4, a);
                uint32_t be[2] = { vf4[0], vf4[1] }, bo2[2] = { vf4[2], vf4[3] };
                mma_fp16(O[2 * jp], pf, be);
                mma_fp16(O[2 * jp + 1], pf, bo2);
            }
        }

        __syncthreads();
        if (t + 2 < ntiles) ISSUE_STAGE(t + 2);
        CP_COMMIT();
    }

    float l0 = l0p, l1 = l1p;
    l0 += __shfl_xor_sync(0xFFFFFFFFu, l0, 1);
    l0 += __shfl_xor_sync(0xFFFFFFFFu, l0, 2);
    l1 += __shfl_xor_sync(0xFFFFFFFFu, l1, 1);
    l1 += __shfl_xor_sync(0xFFFFFFFFu, l1, 2);

    float inv0 = 1.0f / l0, inv1 = 1.0f / l1;
    int b = bh >> 4, h = bh & (H_ - 1);
    size_t base0 = ((size_t)b * L_ + r0g) * D_ + h * DK_ + 2 * (lid & 3);
    size_t base1 = base0 + (size_t)8 * D_;
#pragma unroll
    for (int ni = 0; ni < 8; ni++) {
        *(uint32_t*)&Af[base0 + 8 * ni] = pack_f16x2(O[ni][0] * inv0, O[ni][1] * inv0);
        *(uint32_t*)&Af[base1 + 8 * ni] = pack_f16x2(O[ni][2] * inv1, O[ni][3] * inv1);
    }
#undef ISSUE_STAGE
}

// ---------------------------------------------------------------------------
// Launch.  Inputs: query, key, value, mask, wq, bq, wk, bk, wv, bv, wo, bo
// ---------------------------------------------------------------------------
extern "C" void kernel_launch(void* const* d_in, const int* in_sizes, int n_in,
                              void* d_out, int out_size)
{
    (void)in_sizes; (void)n_in; (void)out_size;
    const float* query = (const float*)d_in[0];
    const float* key   = (const float*)d_in[1];
    const float* value = (const float*)d_in[2];
    const float* wq = (const float*)d_in[4];
    const float* bq = (const float*)d_in[5];
    const float* wk = (const float*)d_in[6];
    const float* bk = (const float*)d_in[7];
    const float* wv = (const float*)d_in[8];
    const float* bv = (const float*)d_in[9];
    const float* wo = (const float*)d_in[10];
    const float* bo = (const float*)d_in[11];

    __nv_bfloat16 *pQh, *pQl, *pKh, *pKl;
    __half *pVf, *pWf, *pXf, *pAf;
    cudaGetSymbolAddress((void**)&pQh, g_Qh);
    cudaGetSymbolAddress((void**)&pQl, g_Ql);
    cudaGetSymbolAddress((void**)&pKh, g_KhP);
    cudaGetSymbolAddress((void**)&pKl, g_KlP);
    cudaGetSymbolAddress((void**)&pVf, g_Vf);
    cudaGetSymbolAddress((void**)&pWf, g_Wf);
    cudaGetSymbolAddress((void**)&pXf, g_Xf);
    cudaGetSymbolAddress((void**)&pAf, g_Af);

    cudaFuncSetAttribute(gemm_qkv, cudaFuncAttributeMaxDynamicSharedMemorySize, GEMM_SMEM);
    cudaFuncSetAttribute(gemm_out, cudaFuncAttributeMaxDynamicSharedMemorySize, GEMM_SMEM);
    cudaFuncSetAttribute(attn_mma, cudaFuncAttributeMaxDynamicSharedMemorySize, ATTN_SMEM);

    const size_t WSZ = (size_t)D_ * D_;
    const size_t XSZ = (size_t)M_ * D_;
    __half *w_hi[4], *w_lo[4], *x_f[3];
    for (int i = 0; i < 4; i++) {
        w_hi[i] = pWf + (size_t)(2 * i) * WSZ;
        w_lo[i] = pWf + (size_t)(2 * i + 1) * WSZ;
    }
    for (int i = 0; i < 3; i++) x_f[i] = pXf + (size_t)i * XSZ;

    // Weight splits (z=4) and input converts (z=3)
    {
        WSplitArgs wa = {};
        const float* wsrc[4] = { wq, wk, wv, wo };
        for (int i = 0; i < 4; i++) {
            wa.src[i] = (const float4*)wsrc[i];
            wa.hi[i] = (uint32_t*)w_hi[i];
            wa.lo[i] = (uint32_t*)w_lo[i];
        }
        conv_w_f16<<<dim3(296, 1, 4), 256>>>(wa, (int)(WSZ / 4));

        XConvArgs xa = {};
        const float* xsrc[3] = { query, key, value };
        for (int i = 0; i < 3; i++) {
            xa.src[i] = (const float4*)xsrc[i];
            xa.dst[i] = (uint32_t*)x_f[i];
        }
        conv_x_f16<<<dim3(394, 1, 3), 256>>>(xa, (int)(XSZ / 4));
    }

    // Merged QKV projection (grid.z = 3), 128x256 tiles, 2-mma fp16 scheme
    {
        const float QSCALE = 0.18033688011112042f;   // log2(e) / sqrt(DK)
        QkvArgs qa = {};
        const float* biases[3] = { bq, bk, bv };
        __nv_bfloat16* ohs[3] = { pQh, pKh, (__nv_bfloat16*)pVf };
        __nv_bfloat16* ols[3] = { pQl, pKl, nullptr };
        for (int i = 0; i < 3; i++) {
            qa.a[i] = x_f[i];
            qa.wh[i] = w_hi[i]; qa.wl[i] = w_lo[i];
            qa.bias[i] = biases[i];
            qa.oh[i] = ohs[i]; qa.ol[i] = ols[i];
            qa.scale[i] = (i == 0) ? QSCALE : 1.0f;
        }
        gemm_qkv<<<dim3(D_ / 256, M_ / 128, 3), 256, GEMM_SMEM>>>(qa);
    }

    dim3 agrid(L_ / QROWS, B_ * H_);   // (32, 32)
    attn_mma<<<agrid, 128, ATTN_SMEM>>>(pQh, pQl, pKh, pKl, pVf, pAf);

    gemm_out<<<dim3(D_ / 256, M_ / 128), 256, GEMM_SMEM>>>(
        pAf, w_hi[3], w_lo[3], bo, (float*)d_out);
}

// round 13
// speedup vs baseline: 2.1779x; 1.5449x over previous
#include <cuda_runtime.h>
#include <cuda_fp16.h>
#include <cstdint>
#include <math.h>

// Problem constants
#define B_  2
#define L_  2048
#define D_  1024
#define H_  16
#define DK_ 64
#define M_  (B_ * L_)   // 4096

// ---------------------------------------------------------------------------
// Scratch (device globals; no allocation allowed)
// ---------------------------------------------------------------------------
__device__ __half g_Qf[(size_t)M_ * D_];     // [B,H,L,DK] fp16 (scaled)
__device__ __half g_Kf[(size_t)M_ * D_];
__device__ __half g_Vf[(size_t)M_ * D_];
__device__ __half g_Wf[4][(size_t)D_ * D_];  // weights, single fp16 plane
__device__ __half g_Xf[3][(size_t)M_ * D_];  // inputs, single fp16 plane
__device__ __half g_Af[(size_t)M_ * D_];     // attn-out, single fp16 plane

// ---------------------------------------------------------------------------
// PTX helpers
// ---------------------------------------------------------------------------
__device__ __forceinline__ uint32_t smem_u32(const void* p) {
    uint32_t a;
    asm("{ .reg .u64 t; cvta.to.shared.u64 t, %1; cvt.u32.u64 %0, t; }" : "=r"(a) : "l"(p));
    return a;
}

#define CP_ASYNC16(dst, src) \
    asm volatile("cp.async.cg.shared.global [%0], [%1], 16;" :: "r"(dst), "l"(src) : "memory")
#define CP_COMMIT() asm volatile("cp.async.commit_group;" ::: "memory")
#define CP_WAIT1()  asm volatile("cp.async.wait_group 1;" ::: "memory")

__device__ __forceinline__ void ldm_x4(uint32_t* r, uint32_t addr) {
    asm volatile("ldmatrix.sync.aligned.m8n8.x4.shared.b16 {%0,%1,%2,%3}, [%4];"
                 : "=r"(r[0]), "=r"(r[1]), "=r"(r[2]), "=r"(r[3]) : "r"(addr));
}
__device__ __forceinline__ void ldm_x4t(uint32_t* r, uint32_t addr) {
    asm volatile("ldmatrix.sync.aligned.m8n8.x4.trans.shared.b16 {%0,%1,%2,%3}, [%4];"
                 : "=r"(r[0]), "=r"(r[1]), "=r"(r[2]), "=r"(r[3]) : "r"(addr));
}
__device__ __forceinline__ void mma_fp16(float* d, const uint32_t* a, const uint32_t* b) {
    asm volatile("mma.sync.aligned.m16n8k16.row.col.f32.f16.f16.f32 "
                 "{%0,%1,%2,%3}, {%4,%5,%6,%7}, {%8,%9}, {%0,%1,%2,%3};"
                 : "+f"(d[0]), "+f"(d[1]), "+f"(d[2]), "+f"(d[3])
                 : "r"(a[0]), "r"(a[1]), "r"(a[2]), "r"(a[3]), "r"(b[0]), "r"(b[1]));
}

// fast exp2 on FMA pipe, degree-3 poly: valid for t <= 0, clamps below -120.
__device__ __forceinline__ float exp2p(float t) {
    t = fmaxf(t, -120.0f);
    float r = t + 12582912.0f;
    int sc = __float_as_int(r) << 23;
    float f = t - (r - 12582912.0f);
    float p = fmaf(f, 5.5504108665e-2f, 2.4022650696e-1f);
    p = fmaf(f, p, 6.9314718056e-1f);
    p = fmaf(f, p, 1.0f);
    return __int_as_float(__float_as_int(p) + sc);
}

// pack (x0, x1) to f16x2 (x0 low, x1 high)
__device__ __forceinline__ uint32_t pack_f16x2(float x0, float x1) {
    uint32_t d;
    asm("cvt.rn.f16x2.f32 %0, %1, %2;" : "=r"(d) : "f"(x1), "f"(x0));
    return d;
}

// ---------------------------------------------------------------------------
// fp32 -> fp16 convert (grid.z selects tensor; up to 7 tensors)
// ---------------------------------------------------------------------------
struct ConvArgs {
    const float4* src[7];
    uint32_t* dst[7];
    int n4[7];
};
__global__ __launch_bounds__(256) void conv_f16(ConvArgs args)
{
    const int z = blockIdx.z;
    const float4* __restrict__ x = args.src[z];
    uint32_t* __restrict__ d = args.dst[z];
    const int n4 = args.n4[z];
    int i = blockIdx.x * blockDim.x + threadIdx.x;
    int stride = gridDim.x * blockDim.x;
    for (; i < n4; i += stride) {
        float4 v = x[i];
        d[2 * i]     = pack_f16x2(v.x, v.y);
        d[2 * i + 1] = pack_f16x2(v.z, v.w);
    }
}

// ---------------------------------------------------------------------------
// fp16 GEMM tile core: C = A[M,K] @ W[K,N], both single fp16 plane.
// 128(M) x 256(N) block, 8 warps (64x64 warp tiles), 3-stage cp.async, kt=32.
// Stage: A 8KB (two M-rows of 64B packed per 128B smem row, XOR-swizzled),
//        B 16KB (32 k-rows x 512B).   1 mma per (mi,ni,ks).
// ---------------------------------------------------------------------------
#define STG_BYTES 24576
#define BOFF_B    8192
#define GEMM_SMEM (3 * STG_BYTES)      // 73728
#define NKT       (D_ / 32)            // 32

// byte offset of (m-row, c16 chunk 0..3) within the packed A tile
__device__ __forceinline__ uint32_t abyte(int m, int c) {
    return (uint32_t)(m >> 1) * 128u +
           (uint32_t)((((m & 1) * 4 + c) ^ ((m >> 1) & 7)) << 4);
}

__device__ __forceinline__ void gemm_issue_stage(
    uint32_t sb, const __half* Af16, const __half* Wf,
    int bm, int bn, int k0, int tid)
{
    // A tile: 128 rows x 4 c16 = 512 chunks
#pragma unroll
    for (int i = 0; i < 2; i++) {
        int id = tid + i * 256;
        int r = id >> 2, c = id & 3;
        const __half* src = Af16 + (size_t)(bm + r) * D_ + k0 + c * 8;
        CP_ASYNC16(sb + abyte(r, c), src);
    }
    // B tile: 32 k-rows x 32 c16 (256 n-cols) = 1024 chunks
#pragma unroll
    for (int i = 0; i < 4; i++) {
        int id = tid + i * 256;
        int r = id >> 5, c32 = id & 31;
        const __half* src = Wf + (size_t)(k0 + r) * D_ + bn + c32 * 8;
        uint32_t dst = sb + BOFF_B + (uint32_t)r * 512u + (uint32_t)((c32 ^ (r & 7)) << 4);
        CP_ASYNC16(dst, src);
    }
}

__device__ __forceinline__ void gemm_mainloop(
    uint32_t sb0, const __half* Af16, const __half* Wf,
    int bm, int bn, int tid, int wm, int wn, int lid, float acc[4][8][4])
{
#pragma unroll
    for (int s = 0; s < 2; s++) {
        gemm_issue_stage(sb0 + s * STG_BYTES, Af16, Wf, bm, bn, s * 32, tid);
        CP_COMMIT();
    }

    uint32_t stg = 0;
    for (int kt = 0; kt < NKT; kt++) {
        CP_WAIT1();
        __syncthreads();
        const uint32_t sb = sb0 + stg * STG_BYTES;

#pragma unroll
        for (int ks = 0; ks < 2; ks++) {
            uint32_t af[4][4];
#pragma unroll
            for (int mi = 0; mi < 4; mi++) {
                int m = wm + mi * 16 + (lid & 15);
                int c = ks * 2 + (lid >> 4);
                ldm_x4(af[mi], sb + abyte(m, c));
            }
            uint32_t bf[8][2];
#pragma unroll
            for (int nj = 0; nj < 4; nj++) {
                int k = ks * 16 + (lid & 15);
                int c32 = (wn >> 3) + 2 * nj + (lid >> 4);
                uint32_t v4[4];
                ldm_x4t(v4, sb + BOFF_B + (uint32_t)k * 512u +
                            (uint32_t)((c32 ^ (k & 7)) << 4));
                bf[2 * nj][0] = v4[0]; bf[2 * nj][1] = v4[1];
                bf[2 * nj + 1][0] = v4[2]; bf[2 * nj + 1][1] = v4[3];
            }
#pragma unroll
            for (int mi = 0; mi < 4; mi++)
#pragma unroll
                for (int ni = 0; ni < 8; ni++)
                    mma_fp16(acc[mi][ni], af[mi], bf[ni]);
        }

        if (kt + 2 < NKT) {
            uint32_t nstg = stg + 2; if (nstg >= 3) nstg -= 3;
            gemm_issue_stage(sb0 + nstg * STG_BYTES, Af16, Wf, bm, bn, (kt + 2) * 32, tid);
        }
        CP_COMMIT();
        if (++stg == 3) stg = 0;
    }
}

// ---------------------------------------------------------------------------
// Merged QKV projection GEMM: grid.z in {0:Q, 1:K, 2:V}; fp16 plane out.
// ---------------------------------------------------------------------------
struct QkvArgs {
    const __half* a[3];
    const __half* w[3];
    const float* bias[3];
    __half* o[3];
    float scale[3];
};

__global__ __launch_bounds__(256, 1) void gemm_qkv(QkvArgs args)
{
    extern __shared__ char smem[];
    const uint32_t sb0 = smem_u32(smem);
    const int z = blockIdx.z;
    const int tid = threadIdx.x;
    const int wid = tid >> 5, lid = tid & 31;
    const int bm = blockIdx.y * 128, bn = blockIdx.x * 256;
    const int wm = (wid >> 2) * 64, wn = (wid & 3) * 64;

    float acc[4][8][4];
#pragma unroll
    for (int i = 0; i < 4; i++)
#pragma unroll
        for (int j = 0; j < 8; j++)
#pragma unroll
            for (int k = 0; k < 4; k++) acc[i][j][k] = 0.0f;

    gemm_mainloop(sb0, args.a[z], args.w[z], bm, bn, tid, wm, wn, lid, acc);

    const float* bias = args.bias[z];
    __half* Pf = args.o[z];
    const float scale = args.scale[z];
#pragma unroll
    for (int mi = 0; mi < 4; mi++) {
#pragma unroll
        for (int ni = 0; ni < 8; ni++) {
            int r0 = bm + wm + mi * 16 + (lid >> 2);
            int c0 = bn + wn + ni * 8 + (lid & 3) * 2;
            float b0 = __ldg(bias + c0), b1 = __ldg(bias + c0 + 1);
            float v0 = (acc[mi][ni][0] + b0) * scale, v1 = (acc[mi][ni][1] + b1) * scale;
            float v2 = (acc[mi][ni][2] + b0) * scale, v3 = (acc[mi][ni][3] + b1) * scale;
            int h = c0 >> 6, dk = c0 & 63, bb = r0 >> 11, ll = r0 & (L_ - 1);
            size_t base = ((size_t)(bb * H_ + h) * L_) * DK_ + dk;
            *(uint32_t*)&Pf[base + (size_t)ll * DK_] = pack_f16x2(v0, v1);
            *(uint32_t*)&Pf[base + (size_t)(ll + 8) * DK_] = pack_f16x2(v2, v3);
        }
    }
}

// ---------------------------------------------------------------------------
// Final projection GEMM: fp32 out [M,N]
// ---------------------------------------------------------------------------
__global__ __launch_bounds__(256, 1) void gemm_out(
    const __half* __restrict__ Af16, const __half* __restrict__ Wf,
    const float* __restrict__ bias, float* __restrict__ C)
{
    extern __shared__ char smem[];
    const uint32_t sb0 = smem_u32(smem);
    const int tid = threadIdx.x;
    const int wid = tid >> 5, lid = tid & 31;
    const int bm = blockIdx.y * 128, bn = blockIdx.x * 256;
    const int wm = (wid >> 2) * 64, wn = (wid & 3) * 64;

    float acc[4][8][4];
#pragma unroll
    for (int i = 0; i < 4; i++)
#pragma unroll
        for (int j = 0; j < 8; j++)
#pragma unroll
            for (int k = 0; k < 4; k++) acc[i][j][k] = 0.0f;

    gemm_mainloop(sb0, Af16, Wf, bm, bn, tid, wm, wn, lid, acc);

#pragma unroll
    for (int mi = 0; mi < 4; mi++) {
#pragma unroll
        for (int ni = 0; ni < 8; ni++) {
            int r0 = bm + wm + mi * 16 + (lid >> 2);
            int c0 = bn + wn + ni * 8 + (lid & 3) * 2;
            float b0 = __ldg(bias + c0), b1 = __ldg(bias + c0 + 1);
            *(float2*)(C + (size_t)r0 * D_ + c0) =
                make_float2(acc[mi][ni][0] + b0, acc[mi][ni][1] + b1);
            *(float2*)(C + (size_t)(r0 + 8) * D_ + c0) =
                make_float2(acc[mi][ni][2] + b0, acc[mi][ni][3] + b1);
        }
    }
}

// ---------------------------------------------------------------------------
// Tensorized causal flash attention — all-fp16 operands, fp32 accum/softmax.
//   CTA = 64 query rows, 128 threads (4 warps x 16 rows), 2 CTAs/SM.
//   Per tile: 32 QK mma + 32 PV mma.
// smem: Q 8KB @0; 2 stages x (Kf 8KB, Vf 8KB) @8KB.  Total 40KB.
// ---------------------------------------------------------------------------
#define KT 64
#define QROWS 64
#define ASTG 16384
#define AVOFF 8192u
#define ATTN_SMEM (8192 + 2 * ASTG)    // 40960

__global__ __launch_bounds__(128, 2) void attn_mma(
    const __half* __restrict__ Qf, const __half* __restrict__ Kf,
    const __half* __restrict__ Vf, __half* __restrict__ Af)
{
    extern __shared__ char smem[];
    const uint32_t sb = smem_u32(smem);
    const int tid = threadIdx.x, wid = tid >> 5, lid = tid & 31;
    const int qt = gridDim.x - 1 - blockIdx.x;   // heavy tiles first
    const int bh = blockIdx.y;
    const int qbase = qt * QROWS;
    const int ntiles = qt + 1;
    const size_t hbase = (size_t)bh * L_ * DK_;

    // ---- issue Q (group 0): 64 rows x 8 c16 = 512 chunks ----
    {
        const __half* qp = Qf + hbase + (size_t)qbase * DK_;
#pragma unroll
        for (int i = 0; i < 4; i++) {
            int id = tid + i * 128;
            int r = id >> 3, c16 = id & 7;
            const __half* src = qp + (size_t)r * DK_ + c16 * 8;
            uint32_t dst = sb + (uint32_t)r * 128u + (uint32_t)((c16 ^ (r & 7)) << 4);
            CP_ASYNC16(dst, src);
        }
        CP_COMMIT();
    }

    const char* kv[2] = { (const char*)(Kf + hbase), (const char*)(Vf + hbase) };
#define ISSUE_STAGE(t) do {                                                  \
        int _kb = (t) * KT;                                                  \
        uint32_t _so = sb + 8192u + (uint32_t)((t) & 1) * ASTG;              \
        _Pragma("unroll")                                                    \
        for (int _i = 0; _i < 8; _i++) {                                     \
            int _id = tid + _i * 128;                                        \
            int _p = _id >> 9, _rem = _id & 511;                             \
            int _r = _rem >> 3, _c = _rem & 7;                               \
            const char* _s = kv[_p] + (size_t)(_kb + _r) * 128 + _c * 16;    \
            uint32_t _d = _so + (uint32_t)_p * 8192u + (uint32_t)_r * 128u + \
                          (uint32_t)((_c ^ (_r & 7)) << 4);                  \
            CP_ASYNC16(_d, _s);                                              \
        }                                                                    \
    } while (0)

    ISSUE_STAGE(0); CP_COMMIT();
    ISSUE_STAGE(1); CP_COMMIT();

    uint32_t qf[4][4];
    float O[8][4];
#pragma unroll
    for (int i = 0; i < 8; i++)
#pragma unroll
        for (int j = 0; j < 4; j++) O[i][j] = 0.0f;
    float m0 = -1e30f, m1 = -1e30f;
    float l0p = 0.0f, l1p = 0.0f;

    const int r0g = qbase + 16 * wid + (lid >> 2);
    const int wrow0 = qbase + 16 * wid;

    for (int t = 0; t < ntiles; t++) {
        CP_WAIT1();
        __syncthreads();
        const uint32_t so = sb + 8192u + (uint32_t)(t & 1) * ASTG;
        const int kb = t * KT;

        if (t == 0) {
#pragma unroll
            for (int kd = 0; kd < 4; kd++) {
                int row = 16 * wid + (lid & 15);
                int c16 = 2 * kd + (lid >> 4);
                ldm_x4(qf[kd], sb + (uint32_t)row * 128u + (uint32_t)((c16 ^ (row & 7)) << 4));
            }
        }

        // ---- S = Q K^T (fp16) ----
        float S[8][4];
#pragma unroll
        for (int i = 0; i < 8; i++)
#pragma unroll
            for (int j = 0; j < 4; j++) S[i][j] = 0.0f;

#pragma unroll
        for (int kd = 0; kd < 4; kd++) {
#pragma unroll
            for (int p4 = 0; p4 < 4; p4++) {
                int row = p4 * 16 + (lid & 15);
                int c16 = 2 * kd + (lid >> 4);
                uint32_t kf4[4];
                ldm_x4(kf4, so + (uint32_t)row * 128u + (uint32_t)((c16 ^ (row & 7)) << 4));
                uint32_t b0[2] = { kf4[0], kf4[2] }, b1[2] = { kf4[1], kf4[3] };
                mma_fp16(S[2 * p4], qf[kd], b0);
                mma_fp16(S[2 * p4 + 1], qf[kd], b1);
            }
        }

        if (kb + KT > wrow0) {
            int colb = kb + 2 * (lid & 3);
            int r1g = r0g + 8;
#pragma unroll
            for (int ni = 0; ni < 8; ni++) {
                int c = colb + 8 * ni;
                if (c > r0g)     S[ni][0] = -1e30f;
                if (c + 1 > r0g) S[ni][1] = -1e30f;
                if (c > r1g)     S[ni][2] = -1e30f;
                if (c + 1 > r1g) S[ni][3] = -1e30f;
            }
        }

        float t0 = -1e30f, t1 = -1e30f;
#pragma unroll
        for (int ni = 0; ni < 8; ni++) {
            t0 = fmaxf(t0, fmaxf(S[ni][0], S[ni][1]));
            t1 = fmaxf(t1, fmaxf(S[ni][2], S[ni][3]));
        }
        t0 = fmaxf(t0, __shfl_xor_sync(0xFFFFFFFFu, t0, 1));
        t0 = fmaxf(t0, __shfl_xor_sync(0xFFFFFFFFu, t0, 2));
        t1 = fmaxf(t1, __shfl_xor_sync(0xFFFFFFFFu, t1, 1));
        t1 = fmaxf(t1, __shfl_xor_sync(0xFFFFFFFFu, t1, 2));
        float n0 = fmaxf(m0, t0), n1 = fmaxf(m1, t1);
        float c0 = exp2p(m0 - n0), c1 = exp2p(m1 - n1);
        m0 = n0; m1 = n1;
        float s0 = 0.0f, s1 = 0.0f;
#pragma unroll
        for (int ni = 0; ni < 8; ni++) {
            S[ni][0] = exp2p(S[ni][0] - n0); s0 += S[ni][0];
            S[ni][1] = exp2p(S[ni][1] - n0); s0 += S[ni][1];
            S[ni][2] = exp2p(S[ni][2] - n1); s1 += S[ni][2];
            S[ni][3] = exp2p(S[ni][3] - n1); s1 += S[ni][3];
            O[ni][0] *= c0; O[ni][1] *= c0; O[ni][2] *= c1; O[ni][3] *= c1;
        }
        l0p = l0p * c0 + s0;
        l1p = l1p * c1 + s1;

        // ---- O += P V (fp16) ----
#pragma unroll
        for (int ks = 0; ks < 4; ks++) {
            uint32_t pf[4];
            pf[0] = pack_f16x2(S[2 * ks][0], S[2 * ks][1]);
            pf[1] = pack_f16x2(S[2 * ks][2], S[2 * ks][3]);
            pf[2] = pack_f16x2(S[2 * ks + 1][0], S[2 * ks + 1][1]);
            pf[3] = pack_f16x2(S[2 * ks + 1][2], S[2 * ks + 1][3]);
#pragma unroll
            for (int jp = 0; jp < 4; jp++) {
                int row = ks * 16 + (lid & 15);
                int c16 = 2 * jp + (lid >> 4);
                uint32_t vf4[4];
                ldm_x4t(vf4, so + AVOFF + (uint32_t)row * 128u +
                             (uint32_t)((c16 ^ (row & 7)) << 4));
                uint32_t be[2] = { vf4[0], vf4[1] }, bo2[2] = { vf4[2], vf4[3] };
                mma_fp16(O[2 * jp], pf, be);
                mma_fp16(O[2 * jp + 1], pf, bo2);
            }
        }

        __syncthreads();
        if (t + 2 < ntiles) ISSUE_STAGE(t + 2);
        CP_COMMIT();
    }

    float l0 = l0p, l1 = l1p;
    l0 += __shfl_xor_sync(0xFFFFFFFFu, l0, 1);
    l0 += __shfl_xor_sync(0xFFFFFFFFu, l0, 2);
    l1 += __shfl_xor_sync(0xFFFFFFFFu, l1, 1);
    l1 += __shfl_xor_sync(0xFFFFFFFFu, l1, 2);

    float inv0 = 1.0f / l0, inv1 = 1.0f / l1;
    int b = bh >> 4, h = bh & (H_ - 1);
    size_t base0 = ((size_t)b * L_ + r0g) * D_ + h * DK_ + 2 * (lid & 3);
    size_t base1 = base0 + (size_t)8 * D_;
#pragma unroll
    for (int ni = 0; ni < 8; ni++) {
        *(uint32_t*)&Af[base0 + 8 * ni] = pack_f16x2(O[ni][0] * inv0, O[ni][1] * inv0);
        *(uint32_t*)&Af[base1 + 8 * ni] = pack_f16x2(O[ni][2] * inv1, O[ni][3] * inv1);
    }
#undef ISSUE_STAGE
}

// ---------------------------------------------------------------------------
// Launch.  Inputs: query, key, value, mask, wq, bq, wk, bk, wv, bv, wo, bo
// ---------------------------------------------------------------------------
extern "C" void kernel_launch(void* const* d_in, const int* in_sizes, int n_in,
                              void* d_out, int out_size)
{
    (void)in_sizes; (void)n_in; (void)out_size;
    const float* query = (const float*)d_in[0];
    const float* key   = (const float*)d_in[1];
    const float* value = (const float*)d_in[2];
    const float* wq = (const float*)d_in[4];
    const float* bq = (const float*)d_in[5];
    const float* wk = (const float*)d_in[6];
    const float* bk = (const float*)d_in[7];
    const float* wv = (const float*)d_in[8];
    const float* bv = (const float*)d_in[9];
    const float* wo = (const float*)d_in[10];
    const float* bo = (const float*)d_in[11];

    __half *pQf, *pKf, *pVf, *pWf, *pXf, *pAf;
    cudaGetSymbolAddress((void**)&pQf, g_Qf);
    cudaGetSymbolAddress((void**)&pKf, g_Kf);
    cudaGetSymbolAddress((void**)&pVf, g_Vf);
    cudaGetSymbolAddress((void**)&pWf, g_Wf);
    cudaGetSymbolAddress((void**)&pXf, g_Xf);
    cudaGetSymbolAddress((void**)&pAf, g_Af);

    cudaFuncSetAttribute(gemm_qkv, cudaFuncAttributeMaxDynamicSharedMemorySize, GEMM_SMEM);
    cudaFuncSetAttribute(gemm_out, cudaFuncAttributeMaxDynamicSharedMemorySize, GEMM_SMEM);
    cudaFuncSetAttribute(attn_mma, cudaFuncAttributeMaxDynamicSharedMemorySize, ATTN_SMEM);

    const size_t WSZ = (size_t)D_ * D_;
    const size_t XSZ = (size_t)M_ * D_;
    __half *w_f[4], *x_f[3];
    for (int i = 0; i < 4; i++) w_f[i] = pWf + (size_t)i * WSZ;
    for (int i = 0; i < 3; i++) x_f[i] = pXf + (size_t)i * XSZ;

    // Converts: weights (z=0..3) + inputs (z=4..6) in one launch
    {
        ConvArgs ca = {};
        const float* wsrc[4] = { wq, wk, wv, wo };
        for (int i = 0; i < 4; i++) {
            ca.src[i] = (const float4*)wsrc[i];
            ca.dst[i] = (uint32_t*)w_f[i];
            ca.n4[i] = (int)(WSZ / 4);
        }
        const float* xsrc[3] = { query, key, value };
        for (int i = 0; i < 3; i++) {
            ca.src[4 + i] = (const float4*)xsrc[i];
            ca.dst[4 + i] = (uint32_t*)x_f[i];
            ca.n4[4 + i] = (int)(XSZ / 4);
        }
        conv_f16<<<dim3(170, 1, 7), 256>>>(ca);
    }

    // Merged QKV projection (grid.z = 3), 128x256 tiles, single-mma fp16
    {
        const float QSCALE = 0.18033688011112042f;   // log2(e) / sqrt(DK)
        QkvArgs qa = {};
        const float* biases[3] = { bq, bk, bv };
        __half* outs[3] = { pQf, pKf, pVf };
        for (int i = 0; i < 3; i++) {
            qa.a[i] = x_f[i];
            qa.w[i] = w_f[i];
            qa.bias[i] = biases[i];
            qa.o[i] = outs[i];
            qa.scale[i] = (i == 0) ? QSCALE : 1.0f;
        }
        gemm_qkv<<<dim3(D_ / 256, M_ / 128, 3), 256, GEMM_SMEM>>>(qa);
    }

    dim3 agrid(L_ / QROWS, B_ * H_);   // (32, 32)
    attn_mma<<<agrid, 128, ATTN_SMEM>>>(pQf, pKf, pVf, pAf);

    gemm_out<<<dim3(D_ / 256, M_ / 128), 256, GEMM_SMEM>>>(
        pAf, w_f[3], bo, (float*)d_out);
}